// round 8
// baseline (speedup 1.0000x reference)
#include <cuda_runtime.h>
#include <cuda_bf16.h>
#include <cstdint>

#define NB    32
#define LP    2048
#define LDRG  256
#define DD    512
#define GPNUM 512

typedef unsigned short u16;

// ======================= scratch (floats) =======================
//  S    0         (33554432)  bf16 hi|lo logits -> alpha per (b,h) row
//  QPh 33554432  QPl 37748736  KPh 41943040  KPl 46137344
//  VPh 50331648  VPl 54525952
//  QDh 58720256  QDl 60817408  KDh 62914560  KDl 65011712
//  VDh 67108864  VDl 69206016
//  PGH 71303168  PGL 75497472  DRH 79691776  DRL 81788928
//  WH  83886080  WL  84672512
__device__ float g_scratch[85458944];
__device__ unsigned char g_masks[24576];
__device__ int g_flag;

__device__ __forceinline__ u16 bf16bits(float x) {
  __nv_bfloat16 h = __float2bfloat16_rn(x);
  return *reinterpret_cast<u16*>(&h);
}
__device__ __forceinline__ float bf16val(u16 b) {
  __nv_bfloat16 h = *reinterpret_cast<__nv_bfloat16*>(&b);
  return __bfloat162float(h);
}
__device__ __forceinline__ void split2(float v0, float v1, uint32_t& hi, uint32_t& lo) {
  u16 h0 = bf16bits(v0), h1 = bf16bits(v1);
  u16 l0 = bf16bits(v0 - bf16val(h0)), l1 = bf16bits(v1 - bf16val(h1));
  hi = (uint32_t)h0 | ((uint32_t)h1 << 16);
  lo = (uint32_t)l0 | ((uint32_t)l1 << 16);
}

// ======================= masks =======================
__device__ __forceinline__ bool read_mask(const void* p, int i, int f) {
  if (f == 0) return ((const unsigned char*)p)[i] != 0;
  if (f == 1) return ((const int*)p)[i] != 0;
  return ((const float*)p)[i] != 0.0f;
}
__global__ void detect_kernel(const unsigned char* __restrict__ p) {
  int big = 0, off = 0;
  for (int i = 0; i < 1024; ++i) {
    unsigned char c = p[i];
    big |= (c > 1) ? 1 : 0;
    off |= (c != 0 && (i & 3) != 0) ? 1 : 0;
  }
  g_flag = big ? 2 : (off ? 0 : 1);
}
__global__ void mask_kernel(const void* __restrict__ mp, const void* __restrict__ md,
                            float* __restrict__ outMP, float* __restrict__ outMD) {
  int f = g_flag;
  int idx = blockIdx.x * blockDim.x + threadIdx.x;
  if (idx < NB * GPNUM) {
    int b = idx / GPNUM, g = idx % GPNUM;
    int base = b * LP + g * 4;
    bool any = false;
#pragma unroll
    for (int r = 0; r < 4; ++r) any = any || read_mask(mp, base + r, f);
    g_masks[idx] = any ? 1 : 0;
    outMP[idx] = any ? 1.0f : 0.0f;
  } else {
    int j = idx - NB * GPNUM;
    if (j < NB * LDRG) {
      bool v = read_mask(md, j, f);
      g_masks[16384 + j] = v ? 1 : 0;
      outMD[j] = v ? 1.0f : 0.0f;
    }
  }
}

// ============== grouping + conversions (vectorized) ==============
__global__ void group_bf16_v4(const float* __restrict__ P,
                              uint2* __restrict__ H, uint2* __restrict__ L) {
  int idx = blockIdx.x * 256 + threadIdx.x;
  int d4 = idx & 127;
  int g = (idx >> 7) & 511;
  int b = idx >> 16;
  const float* p = P + ((size_t)b * LP + (size_t)g * 4) * DD + d4 * 4;
  float4 x0 = *(const float4*)p;
  float4 x1 = *(const float4*)(p + 512);
  float4 x2 = *(const float4*)(p + 1024);
  float4 x3 = *(const float4*)(p + 1536);
  float v0 = 0.25f * (x0.x + x1.x + x2.x + x3.x);
  float v1 = 0.25f * (x0.y + x1.y + x2.y + x3.y);
  float v2 = 0.25f * (x0.z + x1.z + x2.z + x3.z);
  float v3 = 0.25f * (x0.w + x1.w + x2.w + x3.w);
  uint32_t h01, l01, h23, l23;
  split2(v0, v1, h01, l01);
  split2(v2, v3, h23, l23);
  H[idx] = make_uint2(h01, h23);
  L[idx] = make_uint2(l01, l23);
}

__global__ void cvt_bf16_v4(const float4* __restrict__ X, int n4,
                            uint2* __restrict__ H, uint2* __restrict__ L) {
  int i = blockIdx.x * 256 + threadIdx.x;
  if (i >= n4) return;
  float4 x = X[i];
  uint32_t h01, l01, h23, l23;
  split2(x.x, x.y, h01, l01);
  split2(x.z, x.w, h23, l23);
  H[i] = make_uint2(h01, h23);
  L[i] = make_uint2(l01, l23);
}

// 6 weights in one launch: blockIdx.y selects weight
__global__ void cvt_w6(const float4* w0, const float4* w1, const float4* w2,
                       const float4* w3, const float4* w4, const float4* w5,
                       uint2* __restrict__ H, uint2* __restrict__ L) {
  int wi = blockIdx.y;
  const float4* X = (wi == 0) ? w0 : (wi == 1) ? w1 : (wi == 2) ? w2
                   : (wi == 3) ? w3 : (wi == 4) ? w4 : w5;
  int i = blockIdx.x * 256 + threadIdx.x;  // 65536 float4 per weight
  float4 x = X[i];
  uint32_t h01, l01, h23, l23;
  split2(x.x, x.y, h01, l01);
  split2(x.z, x.w, h23, l23);
  size_t o = (size_t)wi * 65536 + i;
  H[o] = make_uint2(h01, h23);
  L[o] = make_uint2(l01, l23);
}

// ======================= HMMA macro =======================
#define MMA_BF16(c, a, b)                                                      \
  asm volatile("mma.sync.aligned.m16n8k16.row.col.f32.bf16.bf16.f32 "          \
               "{%0,%1,%2,%3}, {%4,%5,%6,%7}, {%8,%9}, {%0,%1,%2,%3};"         \
               : "+f"((c)[0]), "+f"((c)[1]), "+f"((c)[2]), "+f"((c)[3])        \
               : "r"((a)[0]), "r"((a)[1]), "r"((a)[2]), "r"((a)[3]),           \
                 "r"((b)[0]), "r"((b)[1]))

// ====== bf16x3 projection (merged over z = weight idx): C = A @ W^T ======
__global__ __launch_bounds__(256) void gemm_proj_mma(
    const u16* __restrict__ Ah, const u16* __restrict__ Al,
    const u16* __restrict__ Wh0, const u16* __restrict__ Wl0,
    u16* __restrict__ Ch0, size_t zstride, size_t hi2lo) {
  __shared__ __align__(16) u16 Ahs[128][40];
  __shared__ __align__(16) u16 Als[128][40];
  __shared__ __align__(16) u16 Bhs[64][40];
  __shared__ __align__(16) u16 Bls[64][40];

  const int tid = threadIdx.x;
  const int w = tid >> 5, lane = tid & 31;
  const int g = lane >> 2, t4 = lane & 3;
  const int wm = (w >> 1) * 32, wn = (w & 1) * 32;
  const int mBase = blockIdx.x * 128;
  const int nBase = blockIdx.y * 64;
  const int z = blockIdx.z;
  const u16* Wh = Wh0 + (size_t)z * 262144;
  const u16* Wl = Wl0 + (size_t)z * 262144;
  u16* Ch = Ch0 + (size_t)z * zstride;
  u16* Cl = Ch + hi2lo;

  float acc[2][4][4];
#pragma unroll
  for (int mi = 0; mi < 2; ++mi)
#pragma unroll
    for (int j = 0; j < 4; ++j)
#pragma unroll
      for (int q = 0; q < 4; ++q) acc[mi][j][q] = 0.0f;

  for (int k0 = 0; k0 < 512; k0 += 32) {
#pragma unroll
    for (int u = tid; u < 512; u += 256) {
      int row = u >> 2, seg = u & 3;
      size_t ga = (size_t)(mBase + row) * 512 + k0 + seg * 8;
      *(uint4*)&Ahs[row][seg * 8] = *(const uint4*)(Ah + ga);
      *(uint4*)&Als[row][seg * 8] = *(const uint4*)(Al + ga);
    }
    if (tid < 256) {
      int row = tid >> 2, seg = tid & 3;
      size_t ga = (size_t)(nBase + row) * 512 + k0 + seg * 8;
      *(uint4*)&Bhs[row][seg * 8] = *(const uint4*)(Wh + ga);
      *(uint4*)&Bls[row][seg * 8] = *(const uint4*)(Wl + ga);
    }
    __syncthreads();
#pragma unroll
    for (int kk = 0; kk < 32; kk += 16) {
      const int kb = kk + t4 * 2;
      uint32_t ah[2][4], al[2][4];
#pragma unroll
      for (int mi = 0; mi < 2; ++mi) {
        int r0 = wm + mi * 16 + g, r1 = r0 + 8;
        ah[mi][0] = *(const uint32_t*)&Ahs[r0][kb];
        ah[mi][1] = *(const uint32_t*)&Ahs[r1][kb];
        ah[mi][2] = *(const uint32_t*)&Ahs[r0][kb + 8];
        ah[mi][3] = *(const uint32_t*)&Ahs[r1][kb + 8];
        al[mi][0] = *(const uint32_t*)&Als[r0][kb];
        al[mi][1] = *(const uint32_t*)&Als[r1][kb];
        al[mi][2] = *(const uint32_t*)&Als[r0][kb + 8];
        al[mi][3] = *(const uint32_t*)&Als[r1][kb + 8];
      }
      uint32_t bh[4][2], bl[4][2];
#pragma unroll
      for (int j = 0; j < 4; ++j) {
        int n = wn + j * 8 + g;
        bh[j][0] = *(const uint32_t*)&Bhs[n][kb];
        bh[j][1] = *(const uint32_t*)&Bhs[n][kb + 8];
        bl[j][0] = *(const uint32_t*)&Bls[n][kb];
        bl[j][1] = *(const uint32_t*)&Bls[n][kb + 8];
      }
#pragma unroll
      for (int mi = 0; mi < 2; ++mi)
#pragma unroll
        for (int j = 0; j < 4; ++j) {
          MMA_BF16(acc[mi][j], ah[mi], bh[j]);
          MMA_BF16(acc[mi][j], ah[mi], bl[j]);
          MMA_BF16(acc[mi][j], al[mi], bh[j]);
        }
    }
    __syncthreads();
  }

#pragma unroll
  for (int mi = 0; mi < 2; ++mi) {
    int row = mBase + wm + mi * 16 + g;
#pragma unroll
    for (int j = 0; j < 4; ++j) {
      int col = nBase + wn + j * 8 + t4 * 2;
      uint32_t hi, lo;
      split2(acc[mi][j][0], acc[mi][j][1], hi, lo);
      *(uint32_t*)(Ch + (size_t)row * 512 + col) = hi;
      *(uint32_t*)(Cl + (size_t)row * 512 + col) = lo;
      split2(acc[mi][j][2], acc[mi][j][3], hi, lo);
      *(uint32_t*)(Ch + (size_t)(row + 8) * 512 + col) = hi;
      *(uint32_t*)(Cl + (size_t)(row + 8) * 512 + col) = lo;
    }
  }
}

// ====== bf16x3 logits: masked, writes bf16 hi|lo into S rows ======
// S slice per z: Lq rows x (2*Lk) u16  =>  z stride = 2*Lq*Lk u16 (= Lq*Lk floats)
__global__ __launch_bounds__(256) void gemm_logits_mma(
    const u16* __restrict__ Qh, const u16* __restrict__ Ql,
    const u16* __restrict__ Kh, const u16* __restrict__ Kl,
    float* __restrict__ S,
    const unsigned char* __restrict__ mq, const unsigned char* __restrict__ mk,
    int Lq, int Lk) {
  __shared__ __align__(16) u16 Ahs[128][40];
  __shared__ __align__(16) u16 Als[128][40];
  __shared__ __align__(16) u16 Bhs[64][40];
  __shared__ __align__(16) u16 Bls[64][40];

  const int tid = threadIdx.x;
  const int w = tid >> 5, lane = tid & 31;
  const int g = lane >> 2, t4 = lane & 3;
  const int wm = (w >> 1) * 32, wn = (w & 1) * 32;
  const int mBase = blockIdx.x * 128;
  const int nBase = blockIdx.y * 64;
  const int z = blockIdx.z;
  const int b = z >> 3, h = z & 7;
  const u16* Ahg = Qh + (size_t)b * Lq * 512 + h * 64;
  const u16* Alg = Ql + (size_t)b * Lq * 512 + h * 64;
  const u16* Bhg = Kh + (size_t)b * Lk * 512 + h * 64;
  const u16* Blg = Kl + (size_t)b * Lk * 512 + h * 64;
  u16* Sbase = (u16*)S + (size_t)z * 2 * Lq * Lk;   // FIXED stride
  const unsigned char* mqb = mq + b * Lq;
  const unsigned char* mkb = mk + b * Lk;

  float acc[2][4][4];
#pragma unroll
  for (int mi = 0; mi < 2; ++mi)
#pragma unroll
    for (int j = 0; j < 4; ++j)
#pragma unroll
      for (int q = 0; q < 4; ++q) acc[mi][j][q] = 0.0f;

#pragma unroll
  for (int k0 = 0; k0 < 64; k0 += 32) {
#pragma unroll
    for (int u = tid; u < 512; u += 256) {
      int row = u >> 2, seg = u & 3;
      size_t ga = (size_t)(mBase + row) * 512 + k0 + seg * 8;
      *(uint4*)&Ahs[row][seg * 8] = *(const uint4*)(Ahg + ga);
      *(uint4*)&Als[row][seg * 8] = *(const uint4*)(Alg + ga);
    }
    if (tid < 256) {
      int row = tid >> 2, seg = tid & 3;
      size_t ga = (size_t)(nBase + row) * 512 + k0 + seg * 8;
      *(uint4*)&Bhs[row][seg * 8] = *(const uint4*)(Bhg + ga);
      *(uint4*)&Bls[row][seg * 8] = *(const uint4*)(Blg + ga);
    }
    __syncthreads();
#pragma unroll
    for (int kk = 0; kk < 32; kk += 16) {
      const int kb = kk + t4 * 2;
      uint32_t ah[2][4], al[2][4];
#pragma unroll
      for (int mi = 0; mi < 2; ++mi) {
        int r0 = wm + mi * 16 + g, r1 = r0 + 8;
        ah[mi][0] = *(const uint32_t*)&Ahs[r0][kb];
        ah[mi][1] = *(const uint32_t*)&Ahs[r1][kb];
        ah[mi][2] = *(const uint32_t*)&Ahs[r0][kb + 8];
        ah[mi][3] = *(const uint32_t*)&Ahs[r1][kb + 8];
        al[mi][0] = *(const uint32_t*)&Als[r0][kb];
        al[mi][1] = *(const uint32_t*)&Als[r1][kb];
        al[mi][2] = *(const uint32_t*)&Als[r0][kb + 8];
        al[mi][3] = *(const uint32_t*)&Als[r1][kb + 8];
      }
      uint32_t bh[4][2], bl[4][2];
#pragma unroll
      for (int j = 0; j < 4; ++j) {
        int n = wn + j * 8 + g;
        bh[j][0] = *(const uint32_t*)&Bhs[n][kb];
        bh[j][1] = *(const uint32_t*)&Bhs[n][kb + 8];
        bl[j][0] = *(const uint32_t*)&Bls[n][kb];
        bl[j][1] = *(const uint32_t*)&Bls[n][kb + 8];
      }
#pragma unroll
      for (int mi = 0; mi < 2; ++mi)
#pragma unroll
        for (int j = 0; j < 4; ++j) {
          MMA_BF16(acc[mi][j], ah[mi], bh[j]);
          MMA_BF16(acc[mi][j], ah[mi], bl[j]);
          MMA_BF16(acc[mi][j], al[mi], bh[j]);
        }
    }
    __syncthreads();
  }

#pragma unroll
  for (int mi = 0; mi < 2; ++mi) {
    int row = mBase + wm + mi * 16 + g;
    float p0 = mqb[row] ? 0.0f : 1.0e6f;
    float p1 = mqb[row + 8] ? 0.0f : 1.0e6f;
    u16* r0p = Sbase + (size_t)row * 2 * Lk;
    u16* r1p = Sbase + (size_t)(row + 8) * 2 * Lk;
#pragma unroll
    for (int j = 0; j < 4; ++j) {
      int col = nBase + wn + j * 8 + t4 * 2;
      float c0 = mkb[col] ? 0.0f : 1.0e6f;
      float c1 = mkb[col + 1] ? 0.0f : 1.0e6f;
      uint32_t hi, lo;
      split2(acc[mi][j][0] - fmaxf(p0, c0), acc[mi][j][1] - fmaxf(p0, c1), hi, lo);
      *(uint32_t*)(r0p + col) = hi;
      *(uint32_t*)(r0p + Lk + col) = lo;
      split2(acc[mi][j][2] - fmaxf(p1, c0), acc[mi][j][3] - fmaxf(p1, c1), hi, lo);
      *(uint32_t*)(r1p + col) = hi;
      *(uint32_t*)(r1p + Lk + col) = lo;
    }
  }
}

// ---------------- softmax: bf16 hi|lo in S -> alpha fp32 out + bf16 hi/lo in-place ----------------
template <int LK>
__global__ __launch_bounds__(256) void softmax_kernel(
    float* __restrict__ S, const unsigned char* __restrict__ mq,
    float* __restrict__ alphaOut, int Lq) {
  __shared__ float sbuf[8][LK + 1];
  const int l = blockIdx.x, b = blockIdx.y;
  const int tid = threadIdx.x, w = tid >> 5, lane = tid & 31;
  const size_t abase = ((size_t)b * Lq + l) * (size_t)(LK * 8);
  u16* srow = (u16*)S + ((size_t)(b * 8 + w) * Lq + l) * 2 * LK;

  if (!mq[b * Lq + l]) {
    for (int idx = tid; idx < LK * 8; idx += 256) alphaOut[abase + idx] = 0.0f;
    for (int k = lane; k < LK; k += 32) ((uint32_t*)srow)[k] = 0;  // zero hi+lo halves
    return;
  }

  const int nit4 = LK / 128;
  float v[LK / 32];
  float mx = -3.0e38f;
#pragma unroll
  for (int i = 0; i < nit4; ++i) {
    uint2 Hv = *(const uint2*)(srow + lane * 4 + 128 * i);
    uint2 Lv = *(const uint2*)(srow + LK + lane * 4 + 128 * i);
    float a0 = bf16val((u16)(Hv.x & 0xffffu)) + bf16val((u16)(Lv.x & 0xffffu));
    float a1 = bf16val((u16)(Hv.x >> 16)) + bf16val((u16)(Lv.x >> 16));
    float a2 = bf16val((u16)(Hv.y & 0xffffu)) + bf16val((u16)(Lv.y & 0xffffu));
    float a3 = bf16val((u16)(Hv.y >> 16)) + bf16val((u16)(Lv.y >> 16));
    v[4 * i] = a0; v[4 * i + 1] = a1; v[4 * i + 2] = a2; v[4 * i + 3] = a3;
    mx = fmaxf(mx, fmaxf(fmaxf(a0, a1), fmaxf(a2, a3)));
  }
#pragma unroll
  for (int o = 16; o > 0; o >>= 1) mx = fmaxf(mx, __shfl_xor_sync(0xffffffffu, mx, o));
  float sum = 0.0f;
#pragma unroll
  for (int q = 0; q < LK / 32; ++q) { float e = __expf(v[q] - mx); v[q] = e; sum += e; }
#pragma unroll
  for (int o = 16; o > 0; o >>= 1) sum += __shfl_xor_sync(0xffffffffu, sum, o);
  float inv = 1.0f / sum;
#pragma unroll
  for (int i = 0; i < nit4; ++i) {
    float a0 = v[4 * i] * inv, a1 = v[4 * i + 1] * inv;
    float a2 = v[4 * i + 2] * inv, a3 = v[4 * i + 3] * inv;
    int k = lane * 4 + 128 * i;
    sbuf[w][k] = a0; sbuf[w][k + 1] = a1; sbuf[w][k + 2] = a2; sbuf[w][k + 3] = a3;
    uint32_t h01, l01, h23, l23;
    split2(a0, a1, h01, l01);
    split2(a2, a3, h23, l23);
    *(uint2*)(srow + k) = make_uint2(h01, h23);
    *(uint2*)(srow + LK + k) = make_uint2(l01, l23);
  }
  __syncthreads();
#pragma unroll 4
  for (int idx = tid; idx < LK * 8; idx += 256) {
    int k = idx >> 3, h = idx & 7;
    alphaOut[abase + idx] = sbuf[h][k];
  }
}

// ====== bf16x3 AV: Out[b,l,h*64+n] = sum_k alpha[b,h,l,k] V[b,k,h*64+n] ======
__global__ __launch_bounds__(256) void gemm_av_mma(
    const float* __restrict__ S, const u16* __restrict__ Vh, const u16* __restrict__ Vl,
    float* __restrict__ Out, int Lq, int Lk) {
  __shared__ __align__(16) u16 Ahs[128][40];
  __shared__ __align__(16) u16 Als[128][40];
  __shared__ __align__(16) u16 Bhs[64][42];
  __shared__ __align__(16) u16 Bls[64][42];

  const int tid = threadIdx.x;
  const int w = tid >> 5, lane = tid & 31;
  const int g = lane >> 2, t4 = lane & 3;
  const int wm = (w >> 1) * 32, wn = (w & 1) * 32;
  const int mBase = blockIdx.x * 128;
  const int z = blockIdx.z;
  const int b = z >> 3, h = z & 7;
  const u16* Abase = (const u16*)S + (size_t)z * 2 * Lq * Lk;   // FIXED stride
  const size_t vbase = (size_t)b * Lk * 512 + h * 64;
  float* C = Out + (size_t)b * Lq * 512 + h * 64;

  float acc[2][4][4];
#pragma unroll
  for (int mi = 0; mi < 2; ++mi)
#pragma unroll
    for (int j = 0; j < 4; ++j)
#pragma unroll
      for (int q = 0; q < 4; ++q) acc[mi][j][q] = 0.0f;

  for (int k0 = 0; k0 < Lk; k0 += 32) {
#pragma unroll
    for (int u = tid; u < 512; u += 256) {
      int row = u >> 2, seg = u & 3;
      const u16* ar = Abase + (size_t)(mBase + row) * 2 * Lk + k0 + seg * 8;
      *(uint4*)&Ahs[row][seg * 8] = *(const uint4*)ar;
      *(uint4*)&Als[row][seg * 8] = *(const uint4*)(ar + Lk);
    }
#pragma unroll
    for (int u = tid; u < 1024; u += 256) {
      int k = u >> 5, np = (u & 31) * 2;
      size_t ga = vbase + (size_t)(k0 + k) * 512 + np;
      uint32_t vh = *(const uint32_t*)(Vh + ga);
      uint32_t vl = *(const uint32_t*)(Vl + ga);
      Bhs[np][k] = (u16)(vh & 0xffffu);
      Bhs[np + 1][k] = (u16)(vh >> 16);
      Bls[np][k] = (u16)(vl & 0xffffu);
      Bls[np + 1][k] = (u16)(vl >> 16);
    }
    __syncthreads();
#pragma unroll
    for (int kk = 0; kk < 32; kk += 16) {
      const int kb = kk + t4 * 2;
      uint32_t ah[2][4], al[2][4];
#pragma unroll
      for (int mi = 0; mi < 2; ++mi) {
        int r0 = wm + mi * 16 + g, r1 = r0 + 8;
        ah[mi][0] = *(const uint32_t*)&Ahs[r0][kb];
        ah[mi][1] = *(const uint32_t*)&Ahs[r1][kb];
        ah[mi][2] = *(const uint32_t*)&Ahs[r0][kb + 8];
        ah[mi][3] = *(const uint32_t*)&Ahs[r1][kb + 8];
        al[mi][0] = *(const uint32_t*)&Als[r0][kb];
        al[mi][1] = *(const uint32_t*)&Als[r1][kb];
        al[mi][2] = *(const uint32_t*)&Als[r0][kb + 8];
        al[mi][3] = *(const uint32_t*)&Als[r1][kb + 8];
      }
      uint32_t bh[4][2], bl[4][2];
#pragma unroll
      for (int j = 0; j < 4; ++j) {
        int n = wn + j * 8 + g;
        bh[j][0] = *(const uint32_t*)&Bhs[n][kb];
        bh[j][1] = *(const uint32_t*)&Bhs[n][kb + 8];
        bl[j][0] = *(const uint32_t*)&Bls[n][kb];
        bl[j][1] = *(const uint32_t*)&Bls[n][kb + 8];
      }
#pragma unroll
      for (int mi = 0; mi < 2; ++mi)
#pragma unroll
        for (int j = 0; j < 4; ++j) {
          MMA_BF16(acc[mi][j], ah[mi], bh[j]);
          MMA_BF16(acc[mi][j], ah[mi], bl[j]);
          MMA_BF16(acc[mi][j], al[mi], bh[j]);
        }
    }
    __syncthreads();
  }

#pragma unroll
  for (int mi = 0; mi < 2; ++mi) {
    int row = mBase + wm + mi * 16 + g;
#pragma unroll
    for (int j = 0; j < 4; ++j) {
      int col = wn + j * 8 + t4 * 2;
      *(float2*)(C + (size_t)row * 512 + col) = make_float2(acc[mi][j][0], acc[mi][j][1]);
      *(float2*)(C + (size_t)(row + 8) * 512 + col) = make_float2(acc[mi][j][2], acc[mi][j][3]);
    }
  }
}

// ---------------- launch ----------------
extern "C" void kernel_launch(void* const* d_in, const int* in_sizes, int n_in,
                              void* d_out, int out_size) {
  const float* protein = (const float*)d_in[0];
  const float* drug    = (const float*)d_in[1];
  const void*  mpraw   = d_in[2];
  const void*  mdraw   = d_in[3];
  const float* W[6] = {(const float*)d_in[4], (const float*)d_in[5], (const float*)d_in[6],
                       (const float*)d_in[7], (const float*)d_in[8], (const float*)d_in[9]};
  float* out = (float*)d_out;

  float* sc = nullptr;
  cudaGetSymbolAddress((void**)&sc, g_scratch);
  unsigned char* mg = nullptr;
  cudaGetSymbolAddress((void**)&mg, g_masks);

  float* Sb = sc;
  u16* QPh = (u16*)(sc + 33554432);
  u16* QPl = (u16*)(sc + 37748736);
  u16* KPh = (u16*)(sc + 41943040); u16* KPl = (u16*)(sc + 46137344);
  u16* VPh = (u16*)(sc + 50331648); u16* VPl = (u16*)(sc + 54525952);
  u16* QDh = (u16*)(sc + 58720256);
  u16* QDl = (u16*)(sc + 60817408);
  u16* KDh = (u16*)(sc + 62914560); u16* KDl = (u16*)(sc + 65011712);
  u16* VDh = (u16*)(sc + 67108864); u16* VDl = (u16*)(sc + 69206016);
  u16* PGH = (u16*)(sc + 71303168); u16* PGL = (u16*)(sc + 75497472);
  u16* DRH = (u16*)(sc + 79691776); u16* DRL = (u16*)(sc + 81788928);
  u16* WHb = (u16*)(sc + 83886080); u16* WLb = (u16*)(sc + 84672512);
  unsigned char* mpg = mg;
  unsigned char* mdg = mg + 16384;

  const size_t OFF_PROT = 0;
  const size_t OFF_DRUG = 8388608;
  const size_t OFF_MP   = 12582912;
  const size_t OFF_MD   = 12599296;
  const size_t OFF_APD  = 12607488;
  const size_t OFF_ADP  = 46161920;

  detect_kernel<<<1, 1>>>((const unsigned char*)mpraw);
  mask_kernel<<<96, 256>>>(mpraw, mdraw, out + OFF_MP, out + OFF_MD);
  group_bf16_v4<<<8192, 256>>>(protein, (uint2*)PGH, (uint2*)PGL);
  cvt_bf16_v4<<<4096, 256>>>((const float4*)drug, 1048576, (uint2*)DRH, (uint2*)DRL);
  cvt_w6<<<dim3(256, 6), 256>>>((const float4*)W[0], (const float4*)W[1], (const float4*)W[2],
                                (const float4*)W[3], (const float4*)W[4], (const float4*)W[5],
                                (uint2*)WHb, (uint2*)WLb);

  // projections (z = Q/K/V): protein uses weights 0..2, drug 3..5
  gemm_proj_mma<<<dim3(128, 8, 3), 256>>>(PGH, PGL, WHb, WLb,
                                          QPh, 16777216u, 8388608u);
  gemm_proj_mma<<<dim3(64, 8, 3), 256>>>(DRH, DRL, WHb + 3 * 262144, WLb + 3 * 262144,
                                         QDh, 8388608u, 4194304u);

  // protein->drug: Lq=512, Lk=256
  gemm_logits_mma<<<dim3(4, 4, 256), 256>>>(QPh, QPl, KDh, KDl, Sb, mpg, mdg, 512, 256);
  softmax_kernel<256><<<dim3(512, 32), 256>>>(Sb, mpg, out + OFF_APD, 512);
  gemm_av_mma<<<dim3(4, 1, 256), 256>>>(Sb, VDh, VDl, out + OFF_PROT, 512, 256);

  // drug->protein: Lq=256, Lk=512
  gemm_logits_mma<<<dim3(2, 8, 256), 256>>>(QDh, QDl, KPh, KPl, Sb, mdg, mpg, 256, 512);
  softmax_kernel<512><<<dim3(256, 32), 256>>>(Sb, mdg, out + OFF_ADP, 256);
  gemm_av_mma<<<dim3(2, 1, 256), 256>>>(Sb, VPh, VPl, out + OFF_DRUG, 256, 512);

  (void)in_sizes; (void)n_in; (void)out_size;
}

// round 9
// speedup vs baseline: 1.5645x; 1.5645x over previous
#include <cuda_runtime.h>
#include <cuda_bf16.h>
#include <cstdint>

#define NB    32
#define LP    2048
#define LDRG  256
#define DD    512
#define GPNUM 512

typedef unsigned short u16;

// ======================= scratch (floats) =======================
//  S    0         (33554432)  fp32 logits / in-place alpha bf16 hi|lo
//  QPh 33554432  QPl 37748736  KPh 41943040  KPl 46137344
//  VPh 50331648  VPl 54525952
//  QDh 58720256  QDl 60817408  KDh 62914560  KDl 65011712
//  VDh 67108864  VDl 69206016
//  PGH 71303168  PGL 75497472  DRH 79691776  DRL 81788928
//  WH  83886080  WL  84672512
__device__ float g_scratch[85458944];
__device__ unsigned char g_masks[24576];
__device__ int g_flag;

__device__ __forceinline__ u16 bf16bits(float x) {
  __nv_bfloat16 h = __float2bfloat16_rn(x);
  return *reinterpret_cast<u16*>(&h);
}
__device__ __forceinline__ float bf16val(u16 b) {
  __nv_bfloat16 h = *reinterpret_cast<__nv_bfloat16*>(&b);
  return __bfloat162float(h);
}
__device__ __forceinline__ void split2(float v0, float v1, uint32_t& hi, uint32_t& lo) {
  u16 h0 = bf16bits(v0), h1 = bf16bits(v1);
  u16 l0 = bf16bits(v0 - bf16val(h0)), l1 = bf16bits(v1 - bf16val(h1));
  hi = (uint32_t)h0 | ((uint32_t)h1 << 16);
  lo = (uint32_t)l0 | ((uint32_t)l1 << 16);
}

// ======================= masks =======================
__device__ __forceinline__ bool read_mask(const void* p, int i, int f) {
  if (f == 0) return ((const unsigned char*)p)[i] != 0;
  if (f == 1) return ((const int*)p)[i] != 0;
  return ((const float*)p)[i] != 0.0f;
}
__global__ void detect_kernel(const unsigned char* __restrict__ p) {
  int big = 0, off = 0;
  for (int i = 0; i < 1024; ++i) {
    unsigned char c = p[i];
    big |= (c > 1) ? 1 : 0;
    off |= (c != 0 && (i & 3) != 0) ? 1 : 0;
  }
  g_flag = big ? 2 : (off ? 0 : 1);
}
__global__ void mask_kernel(const void* __restrict__ mp, const void* __restrict__ md,
                            float* __restrict__ outMP, float* __restrict__ outMD) {
  int f = g_flag;
  int idx = blockIdx.x * blockDim.x + threadIdx.x;
  if (idx < NB * GPNUM) {
    int b = idx / GPNUM, g = idx % GPNUM;
    int base = b * LP + g * 4;
    bool any = false;
#pragma unroll
    for (int r = 0; r < 4; ++r) any = any || read_mask(mp, base + r, f);
    g_masks[idx] = any ? 1 : 0;
    outMP[idx] = any ? 1.0f : 0.0f;
  } else {
    int j = idx - NB * GPNUM;
    if (j < NB * LDRG) {
      bool v = read_mask(md, j, f);
      g_masks[16384 + j] = v ? 1 : 0;
      outMD[j] = v ? 1.0f : 0.0f;
    }
  }
}

// ============== grouping + conversions (vectorized, measured good) ==============
__global__ void group_bf16_v4(const float* __restrict__ P,
                              uint2* __restrict__ H, uint2* __restrict__ L) {
  int idx = blockIdx.x * 256 + threadIdx.x;
  int d4 = idx & 127;
  int g = (idx >> 7) & 511;
  int b = idx >> 16;
  const float* p = P + ((size_t)b * LP + (size_t)g * 4) * DD + d4 * 4;
  float4 x0 = *(const float4*)p;
  float4 x1 = *(const float4*)(p + 512);
  float4 x2 = *(const float4*)(p + 1024);
  float4 x3 = *(const float4*)(p + 1536);
  float v0 = 0.25f * (x0.x + x1.x + x2.x + x3.x);
  float v1 = 0.25f * (x0.y + x1.y + x2.y + x3.y);
  float v2 = 0.25f * (x0.z + x1.z + x2.z + x3.z);
  float v3 = 0.25f * (x0.w + x1.w + x2.w + x3.w);
  uint32_t h01, l01, h23, l23;
  split2(v0, v1, h01, l01);
  split2(v2, v3, h23, l23);
  H[idx] = make_uint2(h01, h23);
  L[idx] = make_uint2(l01, l23);
}

__global__ void cvt_bf16_v4(const float4* __restrict__ X, int n4,
                            uint2* __restrict__ H, uint2* __restrict__ L) {
  int i = blockIdx.x * 256 + threadIdx.x;
  if (i >= n4) return;
  float4 x = X[i];
  uint32_t h01, l01, h23, l23;
  split2(x.x, x.y, h01, l01);
  split2(x.z, x.w, h23, l23);
  H[i] = make_uint2(h01, h23);
  L[i] = make_uint2(l01, l23);
}

__global__ void cvt_w6(const float4* w0, const float4* w1, const float4* w2,
                       const float4* w3, const float4* w4, const float4* w5,
                       uint2* __restrict__ H, uint2* __restrict__ L) {
  int wi = blockIdx.y;
  const float4* X = (wi == 0) ? w0 : (wi == 1) ? w1 : (wi == 2) ? w2
                   : (wi == 3) ? w3 : (wi == 4) ? w4 : w5;
  int i = blockIdx.x * 256 + threadIdx.x;  // 65536 float4 per weight
  float4 x = X[i];
  uint32_t h01, l01, h23, l23;
  split2(x.x, x.y, h01, l01);
  split2(x.z, x.w, h23, l23);
  size_t o = (size_t)wi * 65536 + i;
  H[o] = make_uint2(h01, h23);
  L[o] = make_uint2(l01, l23);
}

// ======================= HMMA macro =======================
#define MMA_BF16(c, a, b)                                                      \
  asm volatile("mma.sync.aligned.m16n8k16.row.col.f32.bf16.bf16.f32 "          \
               "{%0,%1,%2,%3}, {%4,%5,%6,%7}, {%8,%9}, {%0,%1,%2,%3};"         \
               : "+f"((c)[0]), "+f"((c)[1]), "+f"((c)[2]), "+f"((c)[3])        \
               : "r"((a)[0]), "r"((a)[1]), "r"((a)[2]), "r"((a)[3]),           \
                 "r"((b)[0]), "r"((b)[1]))

// ====== bf16x3 projection: C[M,512] = A[M,512] @ W[512,512]^T, bf16 hi/lo out ======
__global__ __launch_bounds__(256) void gemm_proj_mma(
    const u16* __restrict__ Ah, const u16* __restrict__ Al,
    const u16* __restrict__ Wh, const u16* __restrict__ Wl,
    u16* __restrict__ Ch, u16* __restrict__ Cl) {
  __shared__ __align__(16) u16 Ahs[128][40];
  __shared__ __align__(16) u16 Als[128][40];
  __shared__ __align__(16) u16 Bhs[64][40];
  __shared__ __align__(16) u16 Bls[64][40];

  const int tid = threadIdx.x;
  const int w = tid >> 5, lane = tid & 31;
  const int g = lane >> 2, t4 = lane & 3;
  const int wm = (w >> 1) * 32, wn = (w & 1) * 32;
  const int mBase = blockIdx.x * 128;
  const int nBase = blockIdx.y * 64;

  float acc[2][4][4];
#pragma unroll
  for (int mi = 0; mi < 2; ++mi)
#pragma unroll
    for (int j = 0; j < 4; ++j)
#pragma unroll
      for (int q = 0; q < 4; ++q) acc[mi][j][q] = 0.0f;

  for (int k0 = 0; k0 < 512; k0 += 32) {
#pragma unroll
    for (int u = tid; u < 512; u += 256) {
      int row = u >> 2, seg = u & 3;
      size_t ga = (size_t)(mBase + row) * 512 + k0 + seg * 8;
      *(uint4*)&Ahs[row][seg * 8] = *(const uint4*)(Ah + ga);
      *(uint4*)&Als[row][seg * 8] = *(const uint4*)(Al + ga);
    }
    if (tid < 256) {
      int row = tid >> 2, seg = tid & 3;
      size_t ga = (size_t)(nBase + row) * 512 + k0 + seg * 8;
      *(uint4*)&Bhs[row][seg * 8] = *(const uint4*)(Wh + ga);
      *(uint4*)&Bls[row][seg * 8] = *(const uint4*)(Wl + ga);
    }
    __syncthreads();
#pragma unroll
    for (int kk = 0; kk < 32; kk += 16) {
      const int kb = kk + t4 * 2;
      uint32_t ah[2][4], al[2][4];
#pragma unroll
      for (int mi = 0; mi < 2; ++mi) {
        int r0 = wm + mi * 16 + g, r1 = r0 + 8;
        ah[mi][0] = *(const uint32_t*)&Ahs[r0][kb];
        ah[mi][1] = *(const uint32_t*)&Ahs[r1][kb];
        ah[mi][2] = *(const uint32_t*)&Ahs[r0][kb + 8];
        ah[mi][3] = *(const uint32_t*)&Ahs[r1][kb + 8];
        al[mi][0] = *(const uint32_t*)&Als[r0][kb];
        al[mi][1] = *(const uint32_t*)&Als[r1][kb];
        al[mi][2] = *(const uint32_t*)&Als[r0][kb + 8];
        al[mi][3] = *(const uint32_t*)&Als[r1][kb + 8];
      }
      uint32_t bh[4][2], bl[4][2];
#pragma unroll
      for (int j = 0; j < 4; ++j) {
        int n = wn + j * 8 + g;
        bh[j][0] = *(const uint32_t*)&Bhs[n][kb];
        bh[j][1] = *(const uint32_t*)&Bhs[n][kb + 8];
        bl[j][0] = *(const uint32_t*)&Bls[n][kb];
        bl[j][1] = *(const uint32_t*)&Bls[n][kb + 8];
      }
#pragma unroll
      for (int mi = 0; mi < 2; ++mi)
#pragma unroll
        for (int j = 0; j < 4; ++j) {
          MMA_BF16(acc[mi][j], ah[mi], bh[j]);
          MMA_BF16(acc[mi][j], ah[mi], bl[j]);
          MMA_BF16(acc[mi][j], al[mi], bh[j]);
        }
    }
    __syncthreads();
  }

#pragma unroll
  for (int mi = 0; mi < 2; ++mi) {
    int row = mBase + wm + mi * 16 + g;
#pragma unroll
    for (int j = 0; j < 4; ++j) {
      int col = nBase + wn + j * 8 + t4 * 2;
      uint32_t hi, lo;
      split2(acc[mi][j][0], acc[mi][j][1], hi, lo);
      *(uint32_t*)(Ch + (size_t)row * 512 + col) = hi;
      *(uint32_t*)(Cl + (size_t)row * 512 + col) = lo;
      split2(acc[mi][j][2], acc[mi][j][3], hi, lo);
      *(uint32_t*)(Ch + (size_t)(row + 8) * 512 + col) = hi;
      *(uint32_t*)(Cl + (size_t)(row + 8) * 512 + col) = lo;
    }
  }
}

// ====== bf16x3 logits: masked fp32 out into S ======
__global__ __launch_bounds__(256) void gemm_logits_mma(
    const u16* __restrict__ Qh, const u16* __restrict__ Ql,
    const u16* __restrict__ Kh, const u16* __restrict__ Kl,
    float* __restrict__ S,
    const unsigned char* __restrict__ mq, const unsigned char* __restrict__ mk,
    int Lq, int Lk) {
  __shared__ __align__(16) u16 Ahs[128][40];
  __shared__ __align__(16) u16 Als[128][40];
  __shared__ __align__(16) u16 Bhs[64][40];
  __shared__ __align__(16) u16 Bls[64][40];

  const int tid = threadIdx.x;
  const int w = tid >> 5, lane = tid & 31;
  const int g = lane >> 2, t4 = lane & 3;
  const int wm = (w >> 1) * 32, wn = (w & 1) * 32;
  const int mBase = blockIdx.x * 128;
  const int nBase = blockIdx.y * 64;
  const int z = blockIdx.z;
  const int b = z >> 3, h = z & 7;
  const u16* Ahg = Qh + (size_t)b * Lq * 512 + h * 64;
  const u16* Alg = Ql + (size_t)b * Lq * 512 + h * 64;
  const u16* Bhg = Kh + (size_t)b * Lk * 512 + h * 64;
  const u16* Blg = Kl + (size_t)b * Lk * 512 + h * 64;
  float* C = S + (size_t)z * Lq * Lk;
  const unsigned char* mqb = mq + b * Lq;
  const unsigned char* mkb = mk + b * Lk;

  float acc[2][4][4];
#pragma unroll
  for (int mi = 0; mi < 2; ++mi)
#pragma unroll
    for (int j = 0; j < 4; ++j)
#pragma unroll
      for (int q = 0; q < 4; ++q) acc[mi][j][q] = 0.0f;

#pragma unroll
  for (int k0 = 0; k0 < 64; k0 += 32) {
#pragma unroll
    for (int u = tid; u < 512; u += 256) {
      int row = u >> 2, seg = u & 3;
      size_t ga = (size_t)(mBase + row) * 512 + k0 + seg * 8;
      *(uint4*)&Ahs[row][seg * 8] = *(const uint4*)(Ahg + ga);
      *(uint4*)&Als[row][seg * 8] = *(const uint4*)(Alg + ga);
    }
    if (tid < 256) {
      int row = tid >> 2, seg = tid & 3;
      size_t ga = (size_t)(nBase + row) * 512 + k0 + seg * 8;
      *(uint4*)&Bhs[row][seg * 8] = *(const uint4*)(Bhg + ga);
      *(uint4*)&Bls[row][seg * 8] = *(const uint4*)(Blg + ga);
    }
    __syncthreads();
#pragma unroll
    for (int kk = 0; kk < 32; kk += 16) {
      const int kb = kk + t4 * 2;
      uint32_t ah[2][4], al[2][4];
#pragma unroll
      for (int mi = 0; mi < 2; ++mi) {
        int r0 = wm + mi * 16 + g, r1 = r0 + 8;
        ah[mi][0] = *(const uint32_t*)&Ahs[r0][kb];
        ah[mi][1] = *(const uint32_t*)&Ahs[r1][kb];
        ah[mi][2] = *(const uint32_t*)&Ahs[r0][kb + 8];
        ah[mi][3] = *(const uint32_t*)&Ahs[r1][kb + 8];
        al[mi][0] = *(const uint32_t*)&Als[r0][kb];
        al[mi][1] = *(const uint32_t*)&Als[r1][kb];
        al[mi][2] = *(const uint32_t*)&Als[r0][kb + 8];
        al[mi][3] = *(const uint32_t*)&Als[r1][kb + 8];
      }
      uint32_t bh[4][2], bl[4][2];
#pragma unroll
      for (int j = 0; j < 4; ++j) {
        int n = wn + j * 8 + g;
        bh[j][0] = *(const uint32_t*)&Bhs[n][kb];
        bh[j][1] = *(const uint32_t*)&Bhs[n][kb + 8];
        bl[j][0] = *(const uint32_t*)&Bls[n][kb];
        bl[j][1] = *(const uint32_t*)&Bls[n][kb + 8];
      }
#pragma unroll
      for (int mi = 0; mi < 2; ++mi)
#pragma unroll
        for (int j = 0; j < 4; ++j) {
          MMA_BF16(acc[mi][j], ah[mi], bh[j]);
          MMA_BF16(acc[mi][j], ah[mi], bl[j]);
          MMA_BF16(acc[mi][j], al[mi], bh[j]);
        }
    }
    __syncthreads();
  }

#pragma unroll
  for (int mi = 0; mi < 2; ++mi) {
    int row = mBase + wm + mi * 16 + g;
    float p0 = mqb[row] ? 0.0f : 1.0e6f;
    float p1 = mqb[row + 8] ? 0.0f : 1.0e6f;
#pragma unroll
    for (int j = 0; j < 4; ++j) {
      int col = nBase + wn + j * 8 + t4 * 2;
      float c0 = mkb[col] ? 0.0f : 1.0e6f;
      float c1 = mkb[col + 1] ? 0.0f : 1.0e6f;
      *(float2*)(C + (size_t)row * Lk + col) =
          make_float2(acc[mi][j][0] - fmaxf(p0, c0), acc[mi][j][1] - fmaxf(p0, c1));
      *(float2*)(C + (size_t)(row + 8) * Lk + col) =
          make_float2(acc[mi][j][2] - fmaxf(p1, c0), acc[mi][j][3] - fmaxf(p1, c1));
    }
  }
}

// ---------------- softmax: fp32 in S -> alpha fp32 out + bf16 hi/lo in-place ----------------
template <int LK>
__global__ __launch_bounds__(256) void softmax_kernel(
    float* __restrict__ S, const unsigned char* __restrict__ mq,
    float* __restrict__ alphaOut, int Lq) {
  __shared__ float sbuf[8][LK + 1];
  const int l = blockIdx.x, b = blockIdx.y;
  const int tid = threadIdx.x, w = tid >> 5, lane = tid & 31;
  const size_t abase = ((size_t)b * Lq + l) * (size_t)(LK * 8);

  if (!mq[b * Lq + l]) {
    for (int idx = tid; idx < LK * 8; idx += 256) alphaOut[abase + idx] = 0.0f;
#pragma unroll
    for (int h = 0; h < 8; ++h) {
      float* srow = S + ((size_t)(b * 8 + h) * Lq + l) * LK;
      for (int k = tid; k < LK; k += 256) srow[k] = 0.0f;
    }
    return;
  }

  float* srow = S + ((size_t)(b * 8 + w) * Lq + l) * LK;
  const int nit = LK / 32;
  float v[LK / 32];
  float mx = -3.0e38f;
#pragma unroll
  for (int i = 0; i < nit; ++i) { v[i] = srow[lane + 32 * i]; mx = fmaxf(mx, v[i]); }
#pragma unroll
  for (int o = 16; o > 0; o >>= 1) mx = fmaxf(mx, __shfl_xor_sync(0xffffffffu, mx, o));
  float sum = 0.0f;
#pragma unroll
  for (int i = 0; i < nit; ++i) { float e = __expf(v[i] - mx); v[i] = e; sum += e; }
#pragma unroll
  for (int o = 16; o > 0; o >>= 1) sum += __shfl_xor_sync(0xffffffffu, sum, o);
  float inv = 1.0f / sum;
  u16* arow = (u16*)srow;
#pragma unroll
  for (int i = 0; i < nit; ++i) {
    float a = v[i] * inv;
    sbuf[w][lane + 32 * i] = a;
    u16 hb = bf16bits(a);
    arow[lane + 32 * i] = hb;                              // hi half
    arow[LK + lane + 32 * i] = bf16bits(a - bf16val(hb));  // lo half
  }
  __syncthreads();
#pragma unroll 4
  for (int idx = tid; idx < LK * 8; idx += 256) {
    int k = idx >> 3, h = idx & 7;
    alphaOut[abase + idx] = sbuf[h][k];
  }
}

// ====== bf16x3 AV: Out[b,l,h*64+n] = sum_k alpha[b,h,l,k] V[b,k,h*64+n] ======
// alpha stored in-place in S rows as bf16 hi|lo halves.
__global__ __launch_bounds__(256) void gemm_av_mma(
    const float* __restrict__ S, const u16* __restrict__ Vh, const u16* __restrict__ Vl,
    float* __restrict__ Out, int Lq, int Lk) {
  __shared__ __align__(16) u16 Ahs[128][40];
  __shared__ __align__(16) u16 Als[128][40];
  __shared__ __align__(16) u16 Bhs[64][42];
  __shared__ __align__(16) u16 Bls[64][42];

  const int tid = threadIdx.x;
  const int w = tid >> 5, lane = tid & 31;
  const int g = lane >> 2, t4 = lane & 3;
  const int wm = (w >> 1) * 32, wn = (w & 1) * 32;
  const int mBase = blockIdx.x * 128;
  const int z = blockIdx.z;
  const int b = z >> 3, h = z & 7;
  const u16* Abase = (const u16*)(S + (size_t)z * Lq * Lk);  // row: l*2*Lk u16; hi at +k, lo at +Lk+k
  const size_t vbase = (size_t)b * Lk * 512 + h * 64;
  float* C = Out + (size_t)b * Lq * 512 + h * 64;

  float acc[2][4][4];
#pragma unroll
  for (int mi = 0; mi < 2; ++mi)
#pragma unroll
    for (int j = 0; j < 4; ++j)
#pragma unroll
      for (int q = 0; q < 4; ++q) acc[mi][j][q] = 0.0f;

  for (int k0 = 0; k0 < Lk; k0 += 32) {
#pragma unroll
    for (int u = tid; u < 512; u += 256) {
      int row = u >> 2, seg = u & 3;
      const u16* ar = Abase + (size_t)(mBase + row) * 2 * Lk + k0 + seg * 8;
      *(uint4*)&Ahs[row][seg * 8] = *(const uint4*)ar;
      *(uint4*)&Als[row][seg * 8] = *(const uint4*)(ar + Lk);
    }
#pragma unroll
    for (int u = tid; u < 1024; u += 256) {
      int k = u >> 5, np = (u & 31) * 2;
      size_t ga = vbase + (size_t)(k0 + k) * 512 + np;
      uint32_t vh = *(const uint32_t*)(Vh + ga);
      uint32_t vl = *(const uint32_t*)(Vl + ga);
      Bhs[np][k] = (u16)(vh & 0xffffu);
      Bhs[np + 1][k] = (u16)(vh >> 16);
      Bls[np][k] = (u16)(vl & 0xffffu);
      Bls[np + 1][k] = (u16)(vl >> 16);
    }
    __syncthreads();
#pragma unroll
    for (int kk = 0; kk < 32; kk += 16) {
      const int kb = kk + t4 * 2;
      uint32_t ah[2][4], al[2][4];
#pragma unroll
      for (int mi = 0; mi < 2; ++mi) {
        int r0 = wm + mi * 16 + g, r1 = r0 + 8;
        ah[mi][0] = *(const uint32_t*)&Ahs[r0][kb];
        ah[mi][1] = *(const uint32_t*)&Ahs[r1][kb];
        ah[mi][2] = *(const uint32_t*)&Ahs[r0][kb + 8];
        ah[mi][3] = *(const uint32_t*)&Ahs[r1][kb + 8];
        al[mi][0] = *(const uint32_t*)&Als[r0][kb];
        al[mi][1] = *(const uint32_t*)&Als[r1][kb];
        al[mi][2] = *(const uint32_t*)&Als[r0][kb + 8];
        al[mi][3] = *(const uint32_t*)&Als[r1][kb + 8];
      }
      uint32_t bh[4][2], bl[4][2];
#pragma unroll
      for (int j = 0; j < 4; ++j) {
        int n = wn + j * 8 + g;
        bh[j][0] = *(const uint32_t*)&Bhs[n][kb];
        bh[j][1] = *(const uint32_t*)&Bhs[n][kb + 8];
        bl[j][0] = *(const uint32_t*)&Bls[n][kb];
        bl[j][1] = *(const uint32_t*)&Bls[n][kb + 8];
      }
#pragma unroll
      for (int mi = 0; mi < 2; ++mi)
#pragma unroll
        for (int j = 0; j < 4; ++j) {
          MMA_BF16(acc[mi][j], ah[mi], bh[j]);
          MMA_BF16(acc[mi][j], ah[mi], bl[j]);
          MMA_BF16(acc[mi][j], al[mi], bh[j]);
        }
    }
    __syncthreads();
  }

#pragma unroll
  for (int mi = 0; mi < 2; ++mi) {
    int row = mBase + wm + mi * 16 + g;
#pragma unroll
    for (int j = 0; j < 4; ++j) {
      int col = wn + j * 8 + t4 * 2;
      *(float2*)(C + (size_t)row * 512 + col) = make_float2(acc[mi][j][0], acc[mi][j][1]);
      *(float2*)(C + (size_t)(row + 8) * 512 + col) = make_float2(acc[mi][j][2], acc[mi][j][3]);
    }
  }
}

// ---------------- launch ----------------
extern "C" void kernel_launch(void* const* d_in, const int* in_sizes, int n_in,
                              void* d_out, int out_size) {
  const float* protein = (const float*)d_in[0];
  const float* drug    = (const float*)d_in[1];
  const void*  mpraw   = d_in[2];
  const void*  mdraw   = d_in[3];
  const float* W[6] = {(const float*)d_in[4], (const float*)d_in[5], (const float*)d_in[6],
                       (const float*)d_in[7], (const float*)d_in[8], (const float*)d_in[9]};
  float* out = (float*)d_out;

  float* sc = nullptr;
  cudaGetSymbolAddress((void**)&sc, g_scratch);
  unsigned char* mg = nullptr;
  cudaGetSymbolAddress((void**)&mg, g_masks);

  float* Sb = sc;
  u16* QPh = (u16*)(sc + 33554432); u16* QPl = (u16*)(sc + 37748736);
  u16* KPh = (u16*)(sc + 41943040); u16* KPl = (u16*)(sc + 46137344);
  u16* VPh = (u16*)(sc + 50331648); u16* VPl = (u16*)(sc + 54525952);
  u16* QDh = (u16*)(sc + 58720256); u16* QDl = (u16*)(sc + 60817408);
  u16* KDh = (u16*)(sc + 62914560); u16* KDl = (u16*)(sc + 65011712);
  u16* VDh = (u16*)(sc + 67108864); u16* VDl = (u16*)(sc + 69206016);
  u16* PGH = (u16*)(sc + 71303168); u16* PGL = (u16*)(sc + 75497472);
  u16* DRH = (u16*)(sc + 79691776); u16* DRL = (u16*)(sc + 81788928);
  u16* WHb = (u16*)(sc + 83886080); u16* WLb = (u16*)(sc + 84672512);
  unsigned char* mpg = mg;
  unsigned char* mdg = mg + 16384;

  const size_t OFF_PROT = 0;
  const size_t OFF_DRUG = 8388608;
  const size_t OFF_MP   = 12582912;
  const size_t OFF_MD   = 12599296;
  const size_t OFF_APD  = 12607488;
  const size_t OFF_ADP  = 46161920;

  detect_kernel<<<1, 1>>>((const unsigned char*)mpraw);
  mask_kernel<<<96, 256>>>(mpraw, mdraw, out + OFF_MP, out + OFF_MD);
  group_bf16_v4<<<8192, 256>>>(protein, (uint2*)PGH, (uint2*)PGL);
  cvt_bf16_v4<<<4096, 256>>>((const float4*)drug, 1048576, (uint2*)DRH, (uint2*)DRL);
  cvt_w6<<<dim3(256, 6), 256>>>((const float4*)W[0], (const float4*)W[1], (const float4*)W[2],
                                (const float4*)W[3], (const float4*)W[4], (const float4*)W[5],
                                (uint2*)WHb, (uint2*)WLb);

  // projections -> bf16 hi/lo (6 separate launches, R5-proven)
  u16* PH[3] = {QPh, KPh, VPh}; u16* PL[3] = {QPl, KPl, VPl};
  for (int i = 0; i < 3; ++i)
    gemm_proj_mma<<<dim3(128, 8), 256>>>(PGH, PGL, WHb + (size_t)i * 262144,
                                         WLb + (size_t)i * 262144, PH[i], PL[i]);
  u16* DH[3] = {QDh, KDh, VDh}; u16* DL[3] = {QDl, KDl, VDl};
  for (int i = 0; i < 3; ++i)
    gemm_proj_mma<<<dim3(64, 8), 256>>>(DRH, DRL, WHb + (size_t)(i + 3) * 262144,
                                        WLb + (size_t)(i + 3) * 262144, DH[i], DL[i]);

  // protein->drug: Lq=512, Lk=256
  gemm_logits_mma<<<dim3(4, 4, 256), 256>>>(QPh, QPl, KDh, KDl, Sb, mpg, mdg, 512, 256);
  softmax_kernel<256><<<dim3(512, 32), 256>>>(Sb, mpg, out + OFF_APD, 512);
  gemm_av_mma<<<dim3(4, 1, 256), 256>>>(Sb, VDh, VDl, out + OFF_PROT, 512, 256);

  // drug->protein: Lq=256, Lk=512
  gemm_logits_mma<<<dim3(2, 8, 256), 256>>>(QDh, QDl, KPh, KPl, Sb, mdg, mpg, 256, 512);
  softmax_kernel<512><<<dim3(256, 32), 256>>>(Sb, mdg, out + OFF_ADP, 256);
  gemm_av_mma<<<dim3(2, 1, 256), 256>>>(Sb, VPh, VPl, out + OFF_DRUG, 256, 512);

  (void)in_sizes; (void)n_in; (void)out_size;
}

// round 10
// speedup vs baseline: 1.6449x; 1.0514x over previous
#include <cuda_runtime.h>
#include <cuda_bf16.h>
#include <cstdint>

#define NB    32
#define LP    2048
#define LDRG  256
#define DD    512
#define GPNUM 512

typedef unsigned short u16;

// ======================= scratch (floats) =======================
__device__ float g_scratch[85458944];
__device__ unsigned char g_masks[24576];
__device__ int g_flag;

__device__ __forceinline__ u16 bf16bits(float x) {
  __nv_bfloat16 h = __float2bfloat16_rn(x);
  return *reinterpret_cast<u16*>(&h);
}
__device__ __forceinline__ float bf16val(u16 b) {
  __nv_bfloat16 h = *reinterpret_cast<__nv_bfloat16*>(&b);
  return __bfloat162float(h);
}
__device__ __forceinline__ void split2(float v0, float v1, uint32_t& hi, uint32_t& lo) {
  u16 h0 = bf16bits(v0), h1 = bf16bits(v1);
  u16 l0 = bf16bits(v0 - bf16val(h0)), l1 = bf16bits(v1 - bf16val(h1));
  hi = (uint32_t)h0 | ((uint32_t)h1 << 16);
  lo = (uint32_t)l0 | ((uint32_t)l1 << 16);
}
__device__ __forceinline__ uint32_t smaddr(const void* p) {
  return (uint32_t)__cvta_generic_to_shared(p);
}

// ======================= masks =======================
__device__ __forceinline__ bool read_mask(const void* p, int i, int f) {
  if (f == 0) return ((const unsigned char*)p)[i] != 0;
  if (f == 1) return ((const int*)p)[i] != 0;
  return ((const float*)p)[i] != 0.0f;
}
__global__ void detect_kernel(const unsigned char* __restrict__ p) {
  int big = 0, off = 0;
  for (int i = 0; i < 1024; ++i) {
    unsigned char c = p[i];
    big |= (c > 1) ? 1 : 0;
    off |= (c != 0 && (i & 3) != 0) ? 1 : 0;
  }
  g_flag = big ? 2 : (off ? 0 : 1);
}
__global__ void mask_kernel(const void* __restrict__ mp, const void* __restrict__ md,
                            float* __restrict__ outMP, float* __restrict__ outMD) {
  int f = g_flag;
  int idx = blockIdx.x * blockDim.x + threadIdx.x;
  if (idx < NB * GPNUM) {
    int b = idx / GPNUM, g = idx % GPNUM;
    int base = b * LP + g * 4;
    bool any = false;
#pragma unroll
    for (int r = 0; r < 4; ++r) any = any || read_mask(mp, base + r, f);
    g_masks[idx] = any ? 1 : 0;
    outMP[idx] = any ? 1.0f : 0.0f;
  } else {
    int j = idx - NB * GPNUM;
    if (j < NB * LDRG) {
      bool v = read_mask(md, j, f);
      g_masks[16384 + j] = v ? 1 : 0;
      outMD[j] = v ? 1.0f : 0.0f;
    }
  }
}

// ============== grouping + conversions (vectorized) ==============
__global__ void group_bf16_v4(const float* __restrict__ P,
                              uint2* __restrict__ H, uint2* __restrict__ L) {
  int idx = blockIdx.x * 256 + threadIdx.x;
  int d4 = idx & 127;
  int g = (idx >> 7) & 511;
  int b = idx >> 16;
  const float* p = P + ((size_t)b * LP + (size_t)g * 4) * DD + d4 * 4;
  float4 x0 = *(const float4*)p;
  float4 x1 = *(const float4*)(p + 512);
  float4 x2 = *(const float4*)(p + 1024);
  float4 x3 = *(const float4*)(p + 1536);
  float v0 = 0.25f * (x0.x + x1.x + x2.x + x3.x);
  float v1 = 0.25f * (x0.y + x1.y + x2.y + x3.y);
  float v2 = 0.25f * (x0.z + x1.z + x2.z + x3.z);
  float v3 = 0.25f * (x0.w + x1.w + x2.w + x3.w);
  uint32_t h01, l01, h23, l23;
  split2(v0, v1, h01, l01);
  split2(v2, v3, h23, l23);
  H[idx] = make_uint2(h01, h23);
  L[idx] = make_uint2(l01, l23);
}

__global__ void cvt_bf16_v4(const float4* __restrict__ X, int n4,
                            uint2* __restrict__ H, uint2* __restrict__ L) {
  int i = blockIdx.x * 256 + threadIdx.x;
  if (i >= n4) return;
  float4 x = X[i];
  uint32_t h01, l01, h23, l23;
  split2(x.x, x.y, h01, l01);
  split2(x.z, x.w, h23, l23);
  H[i] = make_uint2(h01, h23);
  L[i] = make_uint2(l01, l23);
}

__global__ void cvt_w6(const float4* w0, const float4* w1, const float4* w2,
                       const float4* w3, const float4* w4, const float4* w5,
                       uint2* __restrict__ H, uint2* __restrict__ L) {
  int wi = blockIdx.y;
  const float4* X = (wi == 0) ? w0 : (wi == 1) ? w1 : (wi == 2) ? w2
                   : (wi == 3) ? w3 : (wi == 4) ? w4 : w5;
  int i = blockIdx.x * 256 + threadIdx.x;
  float4 x = X[i];
  uint32_t h01, l01, h23, l23;
  split2(x.x, x.y, h01, l01);
  split2(x.z, x.w, h23, l23);
  size_t o = (size_t)wi * 65536 + i;
  H[o] = make_uint2(h01, h23);
  L[o] = make_uint2(l01, l23);
}

// ======================= MMA / ldmatrix macros =======================
#define MMA_BF16(c, a, b)                                                      \
  asm volatile("mma.sync.aligned.m16n8k16.row.col.f32.bf16.bf16.f32 "          \
               "{%0,%1,%2,%3}, {%4,%5,%6,%7}, {%8,%9}, {%0,%1,%2,%3};"         \
               : "+f"((c)[0]), "+f"((c)[1]), "+f"((c)[2]), "+f"((c)[3])        \
               : "r"((a)[0]), "r"((a)[1]), "r"((a)[2]), "r"((a)[3]),           \
                 "r"((b)[0]), "r"((b)[1]))

#define LDSM_X4(r0, r1, r2, r3, a)                                             \
  asm volatile("ldmatrix.sync.aligned.m8n8.x4.shared.b16 {%0,%1,%2,%3}, [%4];" \
               : "=r"(r0), "=r"(r1), "=r"(r2), "=r"(r3) : "r"(a))

#define LDSM_X4_T(r0, r1, r2, r3, a)                                           \
  asm volatile("ldmatrix.sync.aligned.m8n8.x4.trans.shared.b16 {%0,%1,%2,%3}, [%4];" \
               : "=r"(r0), "=r"(r1), "=r"(r2), "=r"(r3) : "r"(a))

// ====== bf16x3 projection: C[M,512] = A[M,512] @ W[512,512]^T, bf16 hi/lo out ======
__global__ __launch_bounds__(256) void gemm_proj_mma(
    const u16* __restrict__ Ah, const u16* __restrict__ Al,
    const u16* __restrict__ Wh, const u16* __restrict__ Wl,
    u16* __restrict__ Ch, u16* __restrict__ Cl) {
  __shared__ __align__(16) u16 Ahs[128][40];
  __shared__ __align__(16) u16 Als[128][40];
  __shared__ __align__(16) u16 Bhs[64][40];
  __shared__ __align__(16) u16 Bls[64][40];

  const int tid = threadIdx.x;
  const int w = tid >> 5, lane = tid & 31;
  const int g = lane >> 2, t4 = lane & 3;
  const int wm = (w >> 1) * 32, wn = (w & 1) * 32;
  const int mBase = blockIdx.x * 128;
  const int nBase = blockIdx.y * 64;

  // ldmatrix per-lane address components
  const int lane15 = lane & 15;
  const int hi8 = (lane >> 4) << 3;          // 0 or 8
  const uint32_t aAddrH = smaddr(&Ahs[wm + lane15][hi8]);
  const uint32_t aAddrL = smaddr(&Als[wm + lane15][hi8]);
  const int bn = (lane & 7) + hi8;           // row within 16-row pair
  const int bk = lane & 8;                   // k half
  const uint32_t bAddrH = smaddr(&Bhs[wn + bn][bk]);
  const uint32_t bAddrL = smaddr(&Bls[wn + bn][bk]);

  float acc[2][4][4];
#pragma unroll
  for (int mi = 0; mi < 2; ++mi)
#pragma unroll
    for (int j = 0; j < 4; ++j)
#pragma unroll
      for (int q = 0; q < 4; ++q) acc[mi][j][q] = 0.0f;

  for (int k0 = 0; k0 < 512; k0 += 32) {
#pragma unroll
    for (int u = tid; u < 512; u += 256) {
      int row = u >> 2, seg = u & 3;
      size_t ga = (size_t)(mBase + row) * 512 + k0 + seg * 8;
      *(uint4*)&Ahs[row][seg * 8] = *(const uint4*)(Ah + ga);
      *(uint4*)&Als[row][seg * 8] = *(const uint4*)(Al + ga);
    }
    {
      int row = tid >> 2, seg = tid & 3;
      size_t ga = (size_t)(nBase + row) * 512 + k0 + seg * 8;
      *(uint4*)&Bhs[row][seg * 8] = *(const uint4*)(Wh + ga);
      *(uint4*)&Bls[row][seg * 8] = *(const uint4*)(Wl + ga);
    }
    __syncthreads();
#pragma unroll
    for (int kk = 0; kk < 32; kk += 16) {
      uint32_t ah[2][4], al[2][4];
#pragma unroll
      for (int mi = 0; mi < 2; ++mi) {
        LDSM_X4(ah[mi][0], ah[mi][1], ah[mi][2], ah[mi][3], aAddrH + (mi * 640 + kk) * 2);
        LDSM_X4(al[mi][0], al[mi][1], al[mi][2], al[mi][3], aAddrL + (mi * 640 + kk) * 2);
      }
      uint32_t bh[4][2], bl[4][2];
#pragma unroll
      for (int p = 0; p < 2; ++p) {
        LDSM_X4(bh[2 * p][0], bh[2 * p][1], bh[2 * p + 1][0], bh[2 * p + 1][1],
                bAddrH + (p * 640 + kk) * 2);
        LDSM_X4(bl[2 * p][0], bl[2 * p][1], bl[2 * p + 1][0], bl[2 * p + 1][1],
                bAddrL + (p * 640 + kk) * 2);
      }
#pragma unroll
      for (int mi = 0; mi < 2; ++mi)
#pragma unroll
        for (int j = 0; j < 4; ++j) {
          MMA_BF16(acc[mi][j], ah[mi], bh[j]);
          MMA_BF16(acc[mi][j], ah[mi], bl[j]);
          MMA_BF16(acc[mi][j], al[mi], bh[j]);
        }
    }
    __syncthreads();
  }

#pragma unroll
  for (int mi = 0; mi < 2; ++mi) {
    int row = mBase + wm + mi * 16 + g;
#pragma unroll
    for (int j = 0; j < 4; ++j) {
      int col = nBase + wn + j * 8 + t4 * 2;
      uint32_t hi, lo;
      split2(acc[mi][j][0], acc[mi][j][1], hi, lo);
      *(uint32_t*)(Ch + (size_t)row * 512 + col) = hi;
      *(uint32_t*)(Cl + (size_t)row * 512 + col) = lo;
      split2(acc[mi][j][2], acc[mi][j][3], hi, lo);
      *(uint32_t*)(Ch + (size_t)(row + 8) * 512 + col) = hi;
      *(uint32_t*)(Cl + (size_t)(row + 8) * 512 + col) = lo;
    }
  }
}

// ====== bf16x3 logits: masked fp32 out into S ======
__global__ __launch_bounds__(256) void gemm_logits_mma(
    const u16* __restrict__ Qh, const u16* __restrict__ Ql,
    const u16* __restrict__ Kh, const u16* __restrict__ Kl,
    float* __restrict__ S,
    const unsigned char* __restrict__ mq, const unsigned char* __restrict__ mk,
    int Lq, int Lk) {
  __shared__ __align__(16) u16 Ahs[128][40];
  __shared__ __align__(16) u16 Als[128][40];
  __shared__ __align__(16) u16 Bhs[64][40];
  __shared__ __align__(16) u16 Bls[64][40];

  const int tid = threadIdx.x;
  const int w = tid >> 5, lane = tid & 31;
  const int g = lane >> 2, t4 = lane & 3;
  const int wm = (w >> 1) * 32, wn = (w & 1) * 32;
  const int mBase = blockIdx.x * 128;
  const int nBase = blockIdx.y * 64;
  const int z = blockIdx.z;
  const int b = z >> 3, h = z & 7;
  const u16* Ahg = Qh + (size_t)b * Lq * 512 + h * 64;
  const u16* Alg = Ql + (size_t)b * Lq * 512 + h * 64;
  const u16* Bhg = Kh + (size_t)b * Lk * 512 + h * 64;
  const u16* Blg = Kl + (size_t)b * Lk * 512 + h * 64;
  float* C = S + (size_t)z * Lq * Lk;
  const unsigned char* mqb = mq + b * Lq;
  const unsigned char* mkb = mk + b * Lk;

  const int lane15 = lane & 15;
  const int hi8 = (lane >> 4) << 3;
  const uint32_t aAddrH = smaddr(&Ahs[wm + lane15][hi8]);
  const uint32_t aAddrL = smaddr(&Als[wm + lane15][hi8]);
  const int bn = (lane & 7) + hi8;
  const int bk = lane & 8;
  const uint32_t bAddrH = smaddr(&Bhs[wn + bn][bk]);
  const uint32_t bAddrL = smaddr(&Bls[wn + bn][bk]);

  float acc[2][4][4];
#pragma unroll
  for (int mi = 0; mi < 2; ++mi)
#pragma unroll
    for (int j = 0; j < 4; ++j)
#pragma unroll
      for (int q = 0; q < 4; ++q) acc[mi][j][q] = 0.0f;

#pragma unroll
  for (int k0 = 0; k0 < 64; k0 += 32) {
#pragma unroll
    for (int u = tid; u < 512; u += 256) {
      int row = u >> 2, seg = u & 3;
      size_t ga = (size_t)(mBase + row) * 512 + k0 + seg * 8;
      *(uint4*)&Ahs[row][seg * 8] = *(const uint4*)(Ahg + ga);
      *(uint4*)&Als[row][seg * 8] = *(const uint4*)(Alg + ga);
    }
    {
      int row = tid >> 2, seg = tid & 3;
      size_t ga = (size_t)(nBase + row) * 512 + k0 + seg * 8;
      *(uint4*)&Bhs[row][seg * 8] = *(const uint4*)(Bhg + ga);
      *(uint4*)&Bls[row][seg * 8] = *(const uint4*)(Blg + ga);
    }
    __syncthreads();
#pragma unroll
    for (int kk = 0; kk < 32; kk += 16) {
      uint32_t ah[2][4], al[2][4];
#pragma unroll
      for (int mi = 0; mi < 2; ++mi) {
        LDSM_X4(ah[mi][0], ah[mi][1], ah[mi][2], ah[mi][3], aAddrH + (mi * 640 + kk) * 2);
        LDSM_X4(al[mi][0], al[mi][1], al[mi][2], al[mi][3], aAddrL + (mi * 640 + kk) * 2);
      }
      uint32_t bh[4][2], bl[4][2];
#pragma unroll
      for (int p = 0; p < 2; ++p) {
        LDSM_X4(bh[2 * p][0], bh[2 * p][1], bh[2 * p + 1][0], bh[2 * p + 1][1],
                bAddrH + (p * 640 + kk) * 2);
        LDSM_X4(bl[2 * p][0], bl[2 * p][1], bl[2 * p + 1][0], bl[2 * p + 1][1],
                bAddrL + (p * 640 + kk) * 2);
      }
#pragma unroll
      for (int mi = 0; mi < 2; ++mi)
#pragma unroll
        for (int j = 0; j < 4; ++j) {
          MMA_BF16(acc[mi][j], ah[mi], bh[j]);
          MMA_BF16(acc[mi][j], ah[mi], bl[j]);
          MMA_BF16(acc[mi][j], al[mi], bh[j]);
        }
    }
    __syncthreads();
  }

#pragma unroll
  for (int mi = 0; mi < 2; ++mi) {
    int row = mBase + wm + mi * 16 + g;
    float p0 = mqb[row] ? 0.0f : 1.0e6f;
    float p1 = mqb[row + 8] ? 0.0f : 1.0e6f;
#pragma unroll
    for (int j = 0; j < 4; ++j) {
      int col = nBase + wn + j * 8 + t4 * 2;
      float c0 = mkb[col] ? 0.0f : 1.0e6f;
      float c1 = mkb[col + 1] ? 0.0f : 1.0e6f;
      *(float2*)(C + (size_t)row * Lk + col) =
          make_float2(acc[mi][j][0] - fmaxf(p0, c0), acc[mi][j][1] - fmaxf(p0, c1));
      *(float2*)(C + (size_t)(row + 8) * Lk + col) =
          make_float2(acc[mi][j][2] - fmaxf(p1, c0), acc[mi][j][3] - fmaxf(p1, c1));
    }
  }
}

// ---------------- softmax: fp32 in S -> alpha fp32 out + bf16 hi/lo in-place ----------------
template <int LK>
__global__ __launch_bounds__(256) void softmax_kernel(
    float* __restrict__ S, const unsigned char* __restrict__ mq,
    float* __restrict__ alphaOut, int Lq) {
  __shared__ float sbuf[8][LK + 1];
  const int l = blockIdx.x, b = blockIdx.y;
  const int tid = threadIdx.x, w = tid >> 5, lane = tid & 31;
  const size_t abase = ((size_t)b * Lq + l) * (size_t)(LK * 8);

  if (!mq[b * Lq + l]) {
    for (int idx = tid; idx < LK * 8; idx += 256) alphaOut[abase + idx] = 0.0f;
#pragma unroll
    for (int h = 0; h < 8; ++h) {
      float* srow = S + ((size_t)(b * 8 + h) * Lq + l) * LK;
      for (int k = tid; k < LK; k += 256) srow[k] = 0.0f;
    }
    return;
  }

  float* srow = S + ((size_t)(b * 8 + w) * Lq + l) * LK;
  const int nit = LK / 32;
  float v[LK / 32];
  float mx = -3.0e38f;
#pragma unroll
  for (int i = 0; i < nit; ++i) { v[i] = srow[lane + 32 * i]; mx = fmaxf(mx, v[i]); }
#pragma unroll
  for (int o = 16; o > 0; o >>= 1) mx = fmaxf(mx, __shfl_xor_sync(0xffffffffu, mx, o));
  float sum = 0.0f;
#pragma unroll
  for (int i = 0; i < nit; ++i) { float e = __expf(v[i] - mx); v[i] = e; sum += e; }
#pragma unroll
  for (int o = 16; o > 0; o >>= 1) sum += __shfl_xor_sync(0xffffffffu, sum, o);
  float inv = 1.0f / sum;
  u16* arow = (u16*)srow;
#pragma unroll
  for (int i = 0; i < nit; ++i) {
    float a = v[i] * inv;
    sbuf[w][lane + 32 * i] = a;
    u16 hb = bf16bits(a);
    arow[lane + 32 * i] = hb;
    arow[LK + lane + 32 * i] = bf16bits(a - bf16val(hb));
  }
  __syncthreads();
#pragma unroll 4
  for (int idx = tid; idx < LK * 8; idx += 256) {
    int k = idx >> 3, h = idx & 7;
    alphaOut[abase + idx] = sbuf[h][k];
  }
}

// ====== bf16x3 AV: Out[b,l,h*64+n] = sum_k alpha[b,h,l,k] V[b,k,h*64+n] ======
// V tiles stored [k][n] in smem (vectorized), B frags via ldmatrix.trans.
__global__ __launch_bounds__(256) void gemm_av_mma(
    const float* __restrict__ S, const u16* __restrict__ Vh, const u16* __restrict__ Vl,
    float* __restrict__ Out, int Lq, int Lk) {
  __shared__ __align__(16) u16 Ahs[128][40];
  __shared__ __align__(16) u16 Als[128][40];
  __shared__ __align__(16) u16 Bkh[32][72];
  __shared__ __align__(16) u16 Bkl[32][72];

  const int tid = threadIdx.x;
  const int w = tid >> 5, lane = tid & 31;
  const int g = lane >> 2, t4 = lane & 3;
  const int wm = (w >> 1) * 32, wn = (w & 1) * 32;
  const int mBase = blockIdx.x * 128;
  const int z = blockIdx.z;
  const int b = z >> 3, h = z & 7;
  const u16* Abase = (const u16*)(S + (size_t)z * Lq * Lk);  // row l: hi at +k, lo at +Lk+k
  const size_t vbase = (size_t)b * Lk * 512 + h * 64;
  float* C = Out + (size_t)b * Lq * 512 + h * 64;

  const int lane15 = lane & 15;
  const int hi8 = (lane >> 4) << 3;
  const uint32_t aAddrH = smaddr(&Ahs[wm + lane15][hi8]);
  const uint32_t aAddrL = smaddr(&Als[wm + lane15][hi8]);
  // trans-B: per-lane k row and n col
  const int bkOff = (lane & 7) + (lane & 8);   // k within 16
  const uint32_t bAddrH = smaddr(&Bkh[bkOff][wn + hi8]);
  const uint32_t bAddrL = smaddr(&Bkl[bkOff][wn + hi8]);

  float acc[2][4][4];
#pragma unroll
  for (int mi = 0; mi < 2; ++mi)
#pragma unroll
    for (int j = 0; j < 4; ++j)
#pragma unroll
      for (int q = 0; q < 4; ++q) acc[mi][j][q] = 0.0f;

  for (int k0 = 0; k0 < Lk; k0 += 32) {
#pragma unroll
    for (int u = tid; u < 512; u += 256) {
      int row = u >> 2, seg = u & 3;
      const u16* ar = Abase + (size_t)(mBase + row) * 2 * Lk + k0 + seg * 8;
      *(uint4*)&Ahs[row][seg * 8] = *(const uint4*)ar;
      *(uint4*)&Als[row][seg * 8] = *(const uint4*)(ar + Lk);
    }
    {
      // V tile: 32 k-rows x 64 n, natural layout, uint4 copies
      int row = tid >> 3, seg = tid & 7;
      size_t ga = vbase + (size_t)(k0 + row) * 512 + seg * 8;
      *(uint4*)&Bkh[row][seg * 8] = *(const uint4*)(Vh + ga);
      *(uint4*)&Bkl[row][seg * 8] = *(const uint4*)(Vl + ga);
    }
    __syncthreads();
#pragma unroll
    for (int kk = 0; kk < 32; kk += 16) {
      uint32_t ah[2][4], al[2][4];
#pragma unroll
      for (int mi = 0; mi < 2; ++mi) {
        LDSM_X4(ah[mi][0], ah[mi][1], ah[mi][2], ah[mi][3], aAddrH + (mi * 640 + kk) * 2);
        LDSM_X4(al[mi][0], al[mi][1], al[mi][2], al[mi][3], aAddrL + (mi * 640 + kk) * 2);
      }
      uint32_t bh[4][2], bl[4][2];
#pragma unroll
      for (int p = 0; p < 2; ++p) {
        LDSM_X4_T(bh[2 * p][0], bh[2 * p][1], bh[2 * p + 1][0], bh[2 * p + 1][1],
                  bAddrH + (kk * 72 + p * 16) * 2);
        LDSM_X4_T(bl[2 * p][0], bl[2 * p][1], bl[2 * p + 1][0], bl[2 * p + 1][1],
                  bAddrL + (kk * 72 + p * 16) * 2);
      }
#pragma unroll
      for (int mi = 0; mi < 2; ++mi)
#pragma unroll
        for (int j = 0; j < 4; ++j) {
          MMA_BF16(acc[mi][j], ah[mi], bh[j]);
          MMA_BF16(acc[mi][j], ah[mi], bl[j]);
          MMA_BF16(acc[mi][j], al[mi], bh[j]);
        }
    }
    __syncthreads();
  }

#pragma unroll
  for (int mi = 0; mi < 2; ++mi) {
    int row = mBase + wm + mi * 16 + g;
#pragma unroll
    for (int j = 0; j < 4; ++j) {
      int col = wn + j * 8 + t4 * 2;
      *(float2*)(C + (size_t)row * 512 + col) = make_float2(acc[mi][j][0], acc[mi][j][1]);
      *(float2*)(C + (size_t)(row + 8) * 512 + col) = make_float2(acc[mi][j][2], acc[mi][j][3]);
    }
  }
}

// ---------------- launch ----------------
extern "C" void kernel_launch(void* const* d_in, const int* in_sizes, int n_in,
                              void* d_out, int out_size) {
  const float* protein = (const float*)d_in[0];
  const float* drug    = (const float*)d_in[1];
  const void*  mpraw   = d_in[2];
  const void*  mdraw   = d_in[3];
  const float* W[6] = {(const float*)d_in[4], (const float*)d_in[5], (const float*)d_in[6],
                       (const float*)d_in[7], (const float*)d_in[8], (const float*)d_in[9]};
  float* out = (float*)d_out;

  float* sc = nullptr;
  cudaGetSymbolAddress((void**)&sc, g_scratch);
  unsigned char* mg = nullptr;
  cudaGetSymbolAddress((void**)&mg, g_masks);

  float* Sb = sc;
  u16* QPh = (u16*)(sc + 33554432); u16* QPl = (u16*)(sc + 37748736);
  u16* KPh = (u16*)(sc + 41943040); u16* KPl = (u16*)(sc + 46137344);
  u16* VPh = (u16*)(sc + 50331648); u16* VPl = (u16*)(sc + 54525952);
  u16* QDh = (u16*)(sc + 58720256); u16* QDl = (u16*)(sc + 60817408);
  u16* KDh = (u16*)(sc + 62914560); u16* KDl = (u16*)(sc + 65011712);
  u16* VDh = (u16*)(sc + 67108864); u16* VDl = (u16*)(sc + 69206016);
  u16* PGH = (u16*)(sc + 71303168); u16* PGL = (u16*)(sc + 75497472);
  u16* DRH = (u16*)(sc + 79691776); u16* DRL = (u16*)(sc + 81788928);
  u16* WHb = (u16*)(sc + 83886080); u16* WLb = (u16*)(sc + 84672512);
  unsigned char* mpg = mg;
  unsigned char* mdg = mg + 16384;

  const size_t OFF_PROT = 0;
  const size_t OFF_DRUG = 8388608;
  const size_t OFF_MP   = 12582912;
  const size_t OFF_MD   = 12599296;
  const size_t OFF_APD  = 12607488;
  const size_t OFF_ADP  = 46161920;

  detect_kernel<<<1, 1>>>((const unsigned char*)mpraw);
  mask_kernel<<<96, 256>>>(mpraw, mdraw, out + OFF_MP, out + OFF_MD);
  group_bf16_v4<<<8192, 256>>>(protein, (uint2*)PGH, (uint2*)PGL);
  cvt_bf16_v4<<<4096, 256>>>((const float4*)drug, 1048576, (uint2*)DRH, (uint2*)DRL);
  cvt_w6<<<dim3(256, 6), 256>>>((const float4*)W[0], (const float4*)W[1], (const float4*)W[2],
                                (const float4*)W[3], (const float4*)W[4], (const float4*)W[5],
                                (uint2*)WHb, (uint2*)WLb);

  // projections -> bf16 hi/lo (6 separate launches, proven)
  u16* PH[3] = {QPh, KPh, VPh}; u16* PL[3] = {QPl, KPl, VPl};
  for (int i = 0; i < 3; ++i)
    gemm_proj_mma<<<dim3(128, 8), 256>>>(PGH, PGL, WHb + (size_t)i * 262144,
                                         WLb + (size_t)i * 262144, PH[i], PL[i]);
  u16* DH[3] = {QDh, KDh, VDh}; u16* DL[3] = {QDl, KDl, VDl};
  for (int i = 0; i < 3; ++i)
    gemm_proj_mma<<<dim3(64, 8), 256>>>(DRH, DRL, WHb + (size_t)(i + 3) * 262144,
                                        WLb + (size_t)(i + 3) * 262144, DH[i], DL[i]);

  // protein->drug: Lq=512, Lk=256
  gemm_logits_mma<<<dim3(4, 4, 256), 256>>>(QPh, QPl, KDh, KDl, Sb, mpg, mdg, 512, 256);
  softmax_kernel<256><<<dim3(512, 32), 256>>>(Sb, mpg, out + OFF_APD, 512);
  gemm_av_mma<<<dim3(4, 1, 256), 256>>>(Sb, VDh, VDl, out + OFF_PROT, 512, 256);

  // drug->protein: Lq=256, Lk=512
  gemm_logits_mma<<<dim3(2, 8, 256), 256>>>(QDh, QDl, KPh, KPl, Sb, mdg, mpg, 256, 512);
  softmax_kernel<512><<<dim3(256, 32), 256>>>(Sb, mdg, out + OFF_ADP, 256);
  gemm_av_mma<<<dim3(2, 1, 256), 256>>>(Sb, VPh, VPl, out + OFF_DRUG, 256, 512);

  (void)in_sizes; (void)n_in; (void)out_size;
}

// round 11
// speedup vs baseline: 1.8555x; 1.1280x over previous
#include <cuda_runtime.h>
#include <cuda_bf16.h>
#include <cstdint>

#define NB    32
#define LP    2048
#define LDRG  256
#define DD    512
#define GPNUM 512

typedef unsigned short u16;

// ======================= scratch (floats) =======================
__device__ float g_scratch[85458944];
__device__ unsigned char g_masks[24576];
__device__ int g_flag;

__device__ __forceinline__ u16 bf16bits(float x) {
  __nv_bfloat16 h = __float2bfloat16_rn(x);
  return *reinterpret_cast<u16*>(&h);
}
__device__ __forceinline__ float bf16val(u16 b) {
  __nv_bfloat16 h = *reinterpret_cast<__nv_bfloat16*>(&b);
  return __bfloat162float(h);
}
__device__ __forceinline__ void split2(float v0, float v1, uint32_t& hi, uint32_t& lo) {
  u16 h0 = bf16bits(v0), h1 = bf16bits(v1);
  u16 l0 = bf16bits(v0 - bf16val(h0)), l1 = bf16bits(v1 - bf16val(h1));
  hi = (uint32_t)h0 | ((uint32_t)h1 << 16);
  lo = (uint32_t)l0 | ((uint32_t)l1 << 16);
}
__device__ __forceinline__ uint32_t smaddr(const void* p) {
  return (uint32_t)__cvta_generic_to_shared(p);
}

// cp.async helpers
#define CP16(s, g) \
  asm volatile("cp.async.cg.shared.global [%0], [%1], 16;" :: "r"(s), "l"(g))
#define CP_COMMIT() asm volatile("cp.async.commit_group;" ::: "memory")
#define CP_WAIT0() asm volatile("cp.async.wait_group 0;" ::: "memory")
#define CP_WAIT1() asm volatile("cp.async.wait_group 1;" ::: "memory")

// ======================= masks =======================
__device__ __forceinline__ bool read_mask(const void* p, int i, int f) {
  if (f == 0) return ((const unsigned char*)p)[i] != 0;
  if (f == 1) return ((const int*)p)[i] != 0;
  return ((const float*)p)[i] != 0.0f;
}
__global__ void detect_kernel(const unsigned char* __restrict__ p) {
  int big = 0, off = 0;
  for (int i = 0; i < 1024; ++i) {
    unsigned char c = p[i];
    big |= (c > 1) ? 1 : 0;
    off |= (c != 0 && (i & 3) != 0) ? 1 : 0;
  }
  g_flag = big ? 2 : (off ? 0 : 1);
}
__global__ void mask_kernel(const void* __restrict__ mp, const void* __restrict__ md,
                            float* __restrict__ outMP, float* __restrict__ outMD) {
  int f = g_flag;
  int idx = blockIdx.x * blockDim.x + threadIdx.x;
  if (idx < NB * GPNUM) {
    int b = idx / GPNUM, g = idx % GPNUM;
    int base = b * LP + g * 4;
    bool any = false;
#pragma unroll
    for (int r = 0; r < 4; ++r) any = any || read_mask(mp, base + r, f);
    g_masks[idx] = any ? 1 : 0;
    outMP[idx] = any ? 1.0f : 0.0f;
  } else {
    int j = idx - NB * GPNUM;
    if (j < NB * LDRG) {
      bool v = read_mask(md, j, f);
      g_masks[16384 + j] = v ? 1 : 0;
      outMD[j] = v ? 1.0f : 0.0f;
    }
  }
}

// ============== grouping + conversions (vectorized) ==============
__global__ void group_bf16_v4(const float* __restrict__ P,
                              uint2* __restrict__ H, uint2* __restrict__ L) {
  int idx = blockIdx.x * 256 + threadIdx.x;
  int d4 = idx & 127;
  int g = (idx >> 7) & 511;
  int b = idx >> 16;
  const float* p = P + ((size_t)b * LP + (size_t)g * 4) * DD + d4 * 4;
  float4 x0 = *(const float4*)p;
  float4 x1 = *(const float4*)(p + 512);
  float4 x2 = *(const float4*)(p + 1024);
  float4 x3 = *(const float4*)(p + 1536);
  float v0 = 0.25f * (x0.x + x1.x + x2.x + x3.x);
  float v1 = 0.25f * (x0.y + x1.y + x2.y + x3.y);
  float v2 = 0.25f * (x0.z + x1.z + x2.z + x3.z);
  float v3 = 0.25f * (x0.w + x1.w + x2.w + x3.w);
  uint32_t h01, l01, h23, l23;
  split2(v0, v1, h01, l01);
  split2(v2, v3, h23, l23);
  H[idx] = make_uint2(h01, h23);
  L[idx] = make_uint2(l01, l23);
}

__global__ void cvt_bf16_v4(const float4* __restrict__ X, int n4,
                            uint2* __restrict__ H, uint2* __restrict__ L) {
  int i = blockIdx.x * 256 + threadIdx.x;
  if (i >= n4) return;
  float4 x = X[i];
  uint32_t h01, l01, h23, l23;
  split2(x.x, x.y, h01, l01);
  split2(x.z, x.w, h23, l23);
  H[i] = make_uint2(h01, h23);
  L[i] = make_uint2(l01, l23);
}

__global__ void cvt_w6(const float4* w0, const float4* w1, const float4* w2,
                       const float4* w3, const float4* w4, const float4* w5,
                       uint2* __restrict__ H, uint2* __restrict__ L) {
  int wi = blockIdx.y;
  const float4* X = (wi == 0) ? w0 : (wi == 1) ? w1 : (wi == 2) ? w2
                   : (wi == 3) ? w3 : (wi == 4) ? w4 : w5;
  int i = blockIdx.x * 256 + threadIdx.x;
  float4 x = X[i];
  uint32_t h01, l01, h23, l23;
  split2(x.x, x.y, h01, l01);
  split2(x.z, x.w, h23, l23);
  size_t o = (size_t)wi * 65536 + i;
  H[o] = make_uint2(h01, h23);
  L[o] = make_uint2(l01, l23);
}

// ======================= MMA / ldmatrix macros =======================
#define MMA_BF16(c, a, b)                                                      \
  asm volatile("mma.sync.aligned.m16n8k16.row.col.f32.bf16.bf16.f32 "          \
               "{%0,%1,%2,%3}, {%4,%5,%6,%7}, {%8,%9}, {%0,%1,%2,%3};"         \
               : "+f"((c)[0]), "+f"((c)[1]), "+f"((c)[2]), "+f"((c)[3])        \
               : "r"((a)[0]), "r"((a)[1]), "r"((a)[2]), "r"((a)[3]),           \
                 "r"((b)[0]), "r"((b)[1]))

#define LDSM_X4(r0, r1, r2, r3, a)                                             \
  asm volatile("ldmatrix.sync.aligned.m8n8.x4.shared.b16 {%0,%1,%2,%3}, [%4];" \
               : "=r"(r0), "=r"(r1), "=r"(r2), "=r"(r3) : "r"(a))

#define LDSM_X4_T(r0, r1, r2, r3, a)                                           \
  asm volatile("ldmatrix.sync.aligned.m8n8.x4.trans.shared.b16 {%0,%1,%2,%3}, [%4];" \
               : "=r"(r0), "=r"(r1), "=r"(r2), "=r"(r3) : "r"(a))

// ====== bf16x3 projection (cp.async double-buffered) ======
// dyn layout (u16): Ah[2][128*40]=10240, Al 10240, Bh[2][64*40]=5120, Bl 5120
#define PROJ_SMEM 61440
__global__ __launch_bounds__(256) void gemm_proj_mma(
    const u16* __restrict__ Ah, const u16* __restrict__ Al,
    const u16* __restrict__ Wh, const u16* __restrict__ Wl,
    u16* __restrict__ Ch, u16* __restrict__ Cl) {
  extern __shared__ __align__(16) u16 dyn[];
  u16* AhB = dyn;            // + buf*5120
  u16* AlB = dyn + 10240;
  u16* BhB = dyn + 20480;    // + buf*2560
  u16* BlB = dyn + 25600;

  const int tid = threadIdx.x;
  const int w = tid >> 5, lane = tid & 31;
  const int g = lane >> 2, t4 = lane & 3;
  const int wm = (w >> 1) * 32, wn = (w & 1) * 32;
  const int mBase = blockIdx.x * 128;
  const int nBase = blockIdx.y * 64;

  const int lane15 = lane & 15;
  const int hi8 = (lane >> 4) << 3;
  const uint32_t aAddrH = smaddr(AhB + (wm + lane15) * 40 + hi8);
  const uint32_t aAddrL = smaddr(AlB + (wm + lane15) * 40 + hi8);
  const int bn = (lane & 7) + hi8;
  const int bk = lane & 8;
  const uint32_t bAddrH = smaddr(BhB + (wn + bn) * 40 + bk);
  const uint32_t bAddrL = smaddr(BlB + (wn + bn) * 40 + bk);

  auto loadTile = [&](int k0, int buf) {
#pragma unroll
    for (int u = tid; u < 512; u += 256) {
      int row = u >> 2, seg = u & 3;
      size_t ga = (size_t)(mBase + row) * 512 + k0 + seg * 8;
      int so = buf * 5120 + row * 40 + seg * 8;
      CP16(smaddr(AhB + so), Ah + ga);
      CP16(smaddr(AlB + so), Al + ga);
    }
    {
      int row = tid >> 2, seg = tid & 3;
      size_t ga = (size_t)(nBase + row) * 512 + k0 + seg * 8;
      int so = buf * 2560 + row * 40 + seg * 8;
      CP16(smaddr(BhB + so), Wh + ga);
      CP16(smaddr(BlB + so), Wl + ga);
    }
    CP_COMMIT();
  };

  float acc[2][4][4];
#pragma unroll
  for (int mi = 0; mi < 2; ++mi)
#pragma unroll
    for (int j = 0; j < 4; ++j)
#pragma unroll
      for (int q = 0; q < 4; ++q) acc[mi][j][q] = 0.0f;

  loadTile(0, 0);
  for (int t = 0; t < 16; ++t) {
    if (t < 15) { loadTile((t + 1) * 32, (t + 1) & 1); CP_WAIT1(); }
    else CP_WAIT0();
    __syncthreads();
    const uint32_t aOff = (uint32_t)((t & 1) * 10240);
    const uint32_t bOff = (uint32_t)((t & 1) * 5120);
#pragma unroll
    for (int kk = 0; kk < 32; kk += 16) {
      uint32_t ah[2][4], al[2][4];
#pragma unroll
      for (int mi = 0; mi < 2; ++mi) {
        LDSM_X4(ah[mi][0], ah[mi][1], ah[mi][2], ah[mi][3], aAddrH + aOff + (mi * 640 + kk) * 2);
        LDSM_X4(al[mi][0], al[mi][1], al[mi][2], al[mi][3], aAddrL + aOff + (mi * 640 + kk) * 2);
      }
      uint32_t bh[4][2], bl[4][2];
#pragma unroll
      for (int p = 0; p < 2; ++p) {
        LDSM_X4(bh[2 * p][0], bh[2 * p][1], bh[2 * p + 1][0], bh[2 * p + 1][1],
                bAddrH + bOff + (p * 640 + kk) * 2);
        LDSM_X4(bl[2 * p][0], bl[2 * p][1], bl[2 * p + 1][0], bl[2 * p + 1][1],
                bAddrL + bOff + (p * 640 + kk) * 2);
      }
#pragma unroll
      for (int mi = 0; mi < 2; ++mi)
#pragma unroll
        for (int j = 0; j < 4; ++j) {
          MMA_BF16(acc[mi][j], ah[mi], bh[j]);
          MMA_BF16(acc[mi][j], ah[mi], bl[j]);
          MMA_BF16(acc[mi][j], al[mi], bh[j]);
        }
    }
    __syncthreads();
  }

#pragma unroll
  for (int mi = 0; mi < 2; ++mi) {
    int row = mBase + wm + mi * 16 + g;
#pragma unroll
    for (int j = 0; j < 4; ++j) {
      int col = nBase + wn + j * 8 + t4 * 2;
      uint32_t hi, lo;
      split2(acc[mi][j][0], acc[mi][j][1], hi, lo);
      *(uint32_t*)(Ch + (size_t)row * 512 + col) = hi;
      *(uint32_t*)(Cl + (size_t)row * 512 + col) = lo;
      split2(acc[mi][j][2], acc[mi][j][3], hi, lo);
      *(uint32_t*)(Ch + (size_t)(row + 8) * 512 + col) = hi;
      *(uint32_t*)(Cl + (size_t)(row + 8) * 512 + col) = lo;
    }
  }
}

// ====== bf16x3 logits: masked fp32 out into S (R10 proven, static smem) ======
__global__ __launch_bounds__(256) void gemm_logits_mma(
    const u16* __restrict__ Qh, const u16* __restrict__ Ql,
    const u16* __restrict__ Kh, const u16* __restrict__ Kl,
    float* __restrict__ S,
    const unsigned char* __restrict__ mq, const unsigned char* __restrict__ mk,
    int Lq, int Lk) {
  __shared__ __align__(16) u16 Ahs[128][40];
  __shared__ __align__(16) u16 Als[128][40];
  __shared__ __align__(16) u16 Bhs[64][40];
  __shared__ __align__(16) u16 Bls[64][40];

  const int tid = threadIdx.x;
  const int w = tid >> 5, lane = tid & 31;
  const int g = lane >> 2, t4 = lane & 3;
  const int wm = (w >> 1) * 32, wn = (w & 1) * 32;
  const int mBase = blockIdx.x * 128;
  const int nBase = blockIdx.y * 64;
  const int z = blockIdx.z;
  const int b = z >> 3, h = z & 7;
  const u16* Ahg = Qh + (size_t)b * Lq * 512 + h * 64;
  const u16* Alg = Ql + (size_t)b * Lq * 512 + h * 64;
  const u16* Bhg = Kh + (size_t)b * Lk * 512 + h * 64;
  const u16* Blg = Kl + (size_t)b * Lk * 512 + h * 64;
  float* C = S + (size_t)z * Lq * Lk;
  const unsigned char* mqb = mq + b * Lq;
  const unsigned char* mkb = mk + b * Lk;

  const int lane15 = lane & 15;
  const int hi8 = (lane >> 4) << 3;
  const uint32_t aAddrH = smaddr(&Ahs[wm + lane15][hi8]);
  const uint32_t aAddrL = smaddr(&Als[wm + lane15][hi8]);
  const int bn = (lane & 7) + hi8;
  const int bk = lane & 8;
  const uint32_t bAddrH = smaddr(&Bhs[wn + bn][bk]);
  const uint32_t bAddrL = smaddr(&Bls[wn + bn][bk]);

  float acc[2][4][4];
#pragma unroll
  for (int mi = 0; mi < 2; ++mi)
#pragma unroll
    for (int j = 0; j < 4; ++j)
#pragma unroll
      for (int q = 0; q < 4; ++q) acc[mi][j][q] = 0.0f;

#pragma unroll
  for (int k0 = 0; k0 < 64; k0 += 32) {
#pragma unroll
    for (int u = tid; u < 512; u += 256) {
      int row = u >> 2, seg = u & 3;
      size_t ga = (size_t)(mBase + row) * 512 + k0 + seg * 8;
      *(uint4*)&Ahs[row][seg * 8] = *(const uint4*)(Ahg + ga);
      *(uint4*)&Als[row][seg * 8] = *(const uint4*)(Alg + ga);
    }
    {
      int row = tid >> 2, seg = tid & 3;
      size_t ga = (size_t)(nBase + row) * 512 + k0 + seg * 8;
      *(uint4*)&Bhs[row][seg * 8] = *(const uint4*)(Bhg + ga);
      *(uint4*)&Bls[row][seg * 8] = *(const uint4*)(Blg + ga);
    }
    __syncthreads();
#pragma unroll
    for (int kk = 0; kk < 32; kk += 16) {
      uint32_t ah[2][4], al[2][4];
#pragma unroll
      for (int mi = 0; mi < 2; ++mi) {
        LDSM_X4(ah[mi][0], ah[mi][1], ah[mi][2], ah[mi][3], aAddrH + (mi * 640 + kk) * 2);
        LDSM_X4(al[mi][0], al[mi][1], al[mi][2], al[mi][3], aAddrL + (mi * 640 + kk) * 2);
      }
      uint32_t bh[4][2], bl[4][2];
#pragma unroll
      for (int p = 0; p < 2; ++p) {
        LDSM_X4(bh[2 * p][0], bh[2 * p][1], bh[2 * p + 1][0], bh[2 * p + 1][1],
                bAddrH + (p * 640 + kk) * 2);
        LDSM_X4(bl[2 * p][0], bl[2 * p][1], bl[2 * p + 1][0], bl[2 * p + 1][1],
                bAddrL + (p * 640 + kk) * 2);
      }
#pragma unroll
      for (int mi = 0; mi < 2; ++mi)
#pragma unroll
        for (int j = 0; j < 4; ++j) {
          MMA_BF16(acc[mi][j], ah[mi], bh[j]);
          MMA_BF16(acc[mi][j], ah[mi], bl[j]);
          MMA_BF16(acc[mi][j], al[mi], bh[j]);
        }
    }
    __syncthreads();
  }

#pragma unroll
  for (int mi = 0; mi < 2; ++mi) {
    int row = mBase + wm + mi * 16 + g;
    float p0 = mqb[row] ? 0.0f : 1.0e6f;
    float p1 = mqb[row + 8] ? 0.0f : 1.0e6f;
#pragma unroll
    for (int j = 0; j < 4; ++j) {
      int col = nBase + wn + j * 8 + t4 * 2;
      float c0 = mkb[col] ? 0.0f : 1.0e6f;
      float c1 = mkb[col + 1] ? 0.0f : 1.0e6f;
      *(float2*)(C + (size_t)row * Lk + col) =
          make_float2(acc[mi][j][0] - fmaxf(p0, c0), acc[mi][j][1] - fmaxf(p0, c1));
      *(float2*)(C + (size_t)(row + 8) * Lk + col) =
          make_float2(acc[mi][j][2] - fmaxf(p1, c0), acc[mi][j][3] - fmaxf(p1, c1));
    }
  }
}

// ---------------- softmax ----------------
template <int LK>
__global__ __launch_bounds__(256) void softmax_kernel(
    float* __restrict__ S, const unsigned char* __restrict__ mq,
    float* __restrict__ alphaOut, int Lq) {
  __shared__ float sbuf[8][LK + 1];
  const int l = blockIdx.x, b = blockIdx.y;
  const int tid = threadIdx.x, w = tid >> 5, lane = tid & 31;
  const size_t abase = ((size_t)b * Lq + l) * (size_t)(LK * 8);

  if (!mq[b * Lq + l]) {
    for (int idx = tid; idx < LK * 8; idx += 256) alphaOut[abase + idx] = 0.0f;
#pragma unroll
    for (int h = 0; h < 8; ++h) {
      float* srow = S + ((size_t)(b * 8 + h) * Lq + l) * LK;
      for (int k = tid; k < LK; k += 256) srow[k] = 0.0f;
    }
    return;
  }

  float* srow = S + ((size_t)(b * 8 + w) * Lq + l) * LK;
  const int nit = LK / 32;
  float v[LK / 32];
  float mx = -3.0e38f;
#pragma unroll
  for (int i = 0; i < nit; ++i) { v[i] = srow[lane + 32 * i]; mx = fmaxf(mx, v[i]); }
#pragma unroll
  for (int o = 16; o > 0; o >>= 1) mx = fmaxf(mx, __shfl_xor_sync(0xffffffffu, mx, o));
  float sum = 0.0f;
#pragma unroll
  for (int i = 0; i < nit; ++i) { float e = __expf(v[i] - mx); v[i] = e; sum += e; }
#pragma unroll
  for (int o = 16; o > 0; o >>= 1) sum += __shfl_xor_sync(0xffffffffu, sum, o);
  float inv = 1.0f / sum;
  u16* arow = (u16*)srow;
#pragma unroll
  for (int i = 0; i < nit; ++i) {
    float a = v[i] * inv;
    sbuf[w][lane + 32 * i] = a;
    u16 hb = bf16bits(a);
    arow[lane + 32 * i] = hb;
    arow[LK + lane + 32 * i] = bf16bits(a - bf16val(hb));
  }
  __syncthreads();
#pragma unroll 4
  for (int idx = tid; idx < LK * 8; idx += 256) {
    int k = idx >> 3, h = idx & 7;
    alphaOut[abase + idx] = sbuf[h][k];
  }
}

// ====== bf16x3 AV (cp.async double-buffered) ======
// dyn layout (u16): Ah[2][5120], Al[2][5120], Bh[2][2304], Bl[2][2304]
#define AV_SMEM 59392
__global__ __launch_bounds__(256) void gemm_av_mma(
    const float* __restrict__ S, const u16* __restrict__ Vh, const u16* __restrict__ Vl,
    float* __restrict__ Out, int Lq, int Lk) {
  extern __shared__ __align__(16) u16 dyn[];
  u16* AhB = dyn;            // + buf*5120
  u16* AlB = dyn + 10240;
  u16* BhB = dyn + 20480;    // + buf*2304 ; [32][72]
  u16* BlB = dyn + 25088;

  const int tid = threadIdx.x;
  const int w = tid >> 5, lane = tid & 31;
  const int g = lane >> 2, t4 = lane & 3;
  const int wm = (w >> 1) * 32, wn = (w & 1) * 32;
  const int mBase = blockIdx.x * 128;
  const int z = blockIdx.z;
  const int b = z >> 3, h = z & 7;
  const u16* Abase = (const u16*)(S + (size_t)z * Lq * Lk);
  const size_t vbase = (size_t)b * Lk * 512 + h * 64;
  float* C = Out + (size_t)b * Lq * 512 + h * 64;

  const int lane15 = lane & 15;
  const int hi8 = (lane >> 4) << 3;
  const uint32_t aAddrH = smaddr(AhB + (wm + lane15) * 40 + hi8);
  const uint32_t aAddrL = smaddr(AlB + (wm + lane15) * 40 + hi8);
  const int bkOff = (lane & 7) + (lane & 8);
  const uint32_t bAddrH = smaddr(BhB + bkOff * 72 + wn + hi8);
  const uint32_t bAddrL = smaddr(BlB + bkOff * 72 + wn + hi8);

  auto loadTile = [&](int k0, int buf) {
#pragma unroll
    for (int u = tid; u < 512; u += 256) {
      int row = u >> 2, seg = u & 3;
      const u16* ar = Abase + (size_t)(mBase + row) * 2 * Lk + k0 + seg * 8;
      int so = buf * 5120 + row * 40 + seg * 8;
      CP16(smaddr(AhB + so), ar);
      CP16(smaddr(AlB + so), ar + Lk);
    }
    {
      int row = tid >> 3, seg = tid & 7;
      size_t ga = vbase + (size_t)(k0 + row) * 512 + seg * 8;
      int so = buf * 2304 + row * 72 + seg * 8;
      CP16(smaddr(BhB + so), Vh + ga);
      CP16(smaddr(BlB + so), Vl + ga);
    }
    CP_COMMIT();
  };

  float acc[2][4][4];
#pragma unroll
  for (int mi = 0; mi < 2; ++mi)
#pragma unroll
    for (int j = 0; j < 4; ++j)
#pragma unroll
      for (int q = 0; q < 4; ++q) acc[mi][j][q] = 0.0f;

  const int T = Lk / 32;
  loadTile(0, 0);
  for (int t = 0; t < T; ++t) {
    if (t < T - 1) { loadTile((t + 1) * 32, (t + 1) & 1); CP_WAIT1(); }
    else CP_WAIT0();
    __syncthreads();
    const uint32_t aOff = (uint32_t)((t & 1) * 10240);
    const uint32_t bOff = (uint32_t)((t & 1) * 4608);
#pragma unroll
    for (int kk = 0; kk < 32; kk += 16) {
      uint32_t ah[2][4], al[2][4];
#pragma unroll
      for (int mi = 0; mi < 2; ++mi) {
        LDSM_X4(ah[mi][0], ah[mi][1], ah[mi][2], ah[mi][3], aAddrH + aOff + (mi * 640 + kk) * 2);
        LDSM_X4(al[mi][0], al[mi][1], al[mi][2], al[mi][3], aAddrL + aOff + (mi * 640 + kk) * 2);
      }
      uint32_t bh[4][2], bl[4][2];
#pragma unroll
      for (int p = 0; p < 2; ++p) {
        LDSM_X4_T(bh[2 * p][0], bh[2 * p][1], bh[2 * p + 1][0], bh[2 * p + 1][1],
                  bAddrH + bOff + (kk * 72 + p * 16) * 2);
        LDSM_X4_T(bl[2 * p][0], bl[2 * p][1], bl[2 * p + 1][0], bl[2 * p + 1][1],
                  bAddrL + bOff + (kk * 72 + p * 16) * 2);
      }
#pragma unroll
      for (int mi = 0; mi < 2; ++mi)
#pragma unroll
        for (int j = 0; j < 4; ++j) {
          MMA_BF16(acc[mi][j], ah[mi], bh[j]);
          MMA_BF16(acc[mi][j], ah[mi], bl[j]);
          MMA_BF16(acc[mi][j], al[mi], bh[j]);
        }
    }
    __syncthreads();
  }

#pragma unroll
  for (int mi = 0; mi < 2; ++mi) {
    int row = mBase + wm + mi * 16 + g;
#pragma unroll
    for (int j = 0; j < 4; ++j) {
      int col = wn + j * 8 + t4 * 2;
      *(float2*)(C + (size_t)row * 512 + col) = make_float2(acc[mi][j][0], acc[mi][j][1]);
      *(float2*)(C + (size_t)(row + 8) * 512 + col) = make_float2(acc[mi][j][2], acc[mi][j][3]);
    }
  }
}

// ---------------- launch ----------------
extern "C" void kernel_launch(void* const* d_in, const int* in_sizes, int n_in,
                              void* d_out, int out_size) {
  const float* protein = (const float*)d_in[0];
  const float* drug    = (const float*)d_in[1];
  const void*  mpraw   = d_in[2];
  const void*  mdraw   = d_in[3];
  const float* W[6] = {(const float*)d_in[4], (const float*)d_in[5], (const float*)d_in[6],
                       (const float*)d_in[7], (const float*)d_in[8], (const float*)d_in[9]};
  float* out = (float*)d_out;

  float* sc = nullptr;
  cudaGetSymbolAddress((void**)&sc, g_scratch);
  unsigned char* mg = nullptr;
  cudaGetSymbolAddress((void**)&mg, g_masks);

  float* Sb = sc;
  u16* QPh = (u16*)(sc + 33554432); u16* QPl = (u16*)(sc + 37748736);
  u16* KPh = (u16*)(sc + 41943040); u16* KPl = (u16*)(sc + 46137344);
  u16* VPh = (u16*)(sc + 50331648); u16* VPl = (u16*)(sc + 54525952);
  u16* QDh = (u16*)(sc + 58720256); u16* QDl = (u16*)(sc + 60817408);
  u16* KDh = (u16*)(sc + 62914560); u16* KDl = (u16*)(sc + 65011712);
  u16* VDh = (u16*)(sc + 67108864); u16* VDl = (u16*)(sc + 69206016);
  u16* PGH = (u16*)(sc + 71303168); u16* PGL = (u16*)(sc + 75497472);
  u16* DRH = (u16*)(sc + 79691776); u16* DRL = (u16*)(sc + 81788928);
  u16* WHb = (u16*)(sc + 83886080); u16* WLb = (u16*)(sc + 84672512);
  unsigned char* mpg = mg;
  unsigned char* mdg = mg + 16384;

  const size_t OFF_PROT = 0;
  const size_t OFF_DRUG = 8388608;
  const size_t OFF_MP   = 12582912;
  const size_t OFF_MD   = 12599296;
  const size_t OFF_APD  = 12607488;
  const size_t OFF_ADP  = 46161920;

  static int attr_done = 0;
  if (!attr_done) {
    cudaFuncSetAttribute(gemm_proj_mma, cudaFuncAttributeMaxDynamicSharedMemorySize, PROJ_SMEM);
    cudaFuncSetAttribute(gemm_av_mma, cudaFuncAttributeMaxDynamicSharedMemorySize, AV_SMEM);
    attr_done = 1;
  }

  detect_kernel<<<1, 1>>>((const unsigned char*)mpraw);
  mask_kernel<<<96, 256>>>(mpraw, mdraw, out + OFF_MP, out + OFF_MD);
  group_bf16_v4<<<8192, 256>>>(protein, (uint2*)PGH, (uint2*)PGL);
  cvt_bf16_v4<<<4096, 256>>>((const float4*)drug, 1048576, (uint2*)DRH, (uint2*)DRL);
  cvt_w6<<<dim3(256, 6), 256>>>((const float4*)W[0], (const float4*)W[1], (const float4*)W[2],
                                (const float4*)W[3], (const float4*)W[4], (const float4*)W[5],
                                (uint2*)WHb, (uint2*)WLb);

  // projections -> bf16 hi/lo
  u16* PH[3] = {QPh, KPh, VPh}; u16* PL[3] = {QPl, KPl, VPl};
  for (int i = 0; i < 3; ++i)
    gemm_proj_mma<<<dim3(128, 8), 256, PROJ_SMEM>>>(PGH, PGL, WHb + (size_t)i * 262144,
                                                    WLb + (size_t)i * 262144, PH[i], PL[i]);
  u16* DH[3] = {QDh, KDh, VDh}; u16* DL[3] = {QDl, KDl, VDl};
  for (int i = 0; i < 3; ++i)
    gemm_proj_mma<<<dim3(64, 8), 256, PROJ_SMEM>>>(DRH, DRL, WHb + (size_t)(i + 3) * 262144,
                                                   WLb + (size_t)(i + 3) * 262144, DH[i], DL[i]);

  // protein->drug: Lq=512, Lk=256
  gemm_logits_mma<<<dim3(4, 4, 256), 256>>>(QPh, QPl, KDh, KDl, Sb, mpg, mdg, 512, 256);
  softmax_kernel<256><<<dim3(512, 32), 256>>>(Sb, mpg, out + OFF_APD, 512);
  gemm_av_mma<<<dim3(4, 1, 256), 256, AV_SMEM>>>(Sb, VDh, VDl, out + OFF_PROT, 512, 256);

  // drug->protein: Lq=256, Lk=512
  gemm_logits_mma<<<dim3(2, 8, 256), 256>>>(QDh, QDl, KPh, KPl, Sb, mdg, mpg, 256, 512);
  softmax_kernel<512><<<dim3(256, 32), 256>>>(Sb, mdg, out + OFF_ADP, 256);
  gemm_av_mma<<<dim3(2, 1, 256), 256, AV_SMEM>>>(Sb, VPh, VPl, out + OFF_DRUG, 256, 512);

  (void)in_sizes; (void)n_in; (void)out_size;
}

// round 12
// speedup vs baseline: 1.9350x; 1.0429x over previous
#include <cuda_runtime.h>
#include <cuda_bf16.h>
#include <cstdint>

#define NB    32
#define LP    2048
#define LDRG  256
#define DD    512
#define GPNUM 512

typedef unsigned short u16;

// ======================= scratch (floats) =======================
__device__ float g_scratch[85458944];
__device__ unsigned char g_masks[24576];
__device__ int g_flag;

__device__ __forceinline__ u16 bf16bits(float x) {
  __nv_bfloat16 h = __float2bfloat16_rn(x);
  return *reinterpret_cast<u16*>(&h);
}
__device__ __forceinline__ float bf16val(u16 b) {
  __nv_bfloat16 h = *reinterpret_cast<__nv_bfloat16*>(&b);
  return __bfloat162float(h);
}
__device__ __forceinline__ void split2(float v0, float v1, uint32_t& hi, uint32_t& lo) {
  u16 h0 = bf16bits(v0), h1 = bf16bits(v1);
  u16 l0 = bf16bits(v0 - bf16val(h0)), l1 = bf16bits(v1 - bf16val(h1));
  hi = (uint32_t)h0 | ((uint32_t)h1 << 16);
  lo = (uint32_t)l0 | ((uint32_t)l1 << 16);
}
__device__ __forceinline__ uint32_t smaddr(const void* p) {
  return (uint32_t)__cvta_generic_to_shared(p);
}

// cp.async helpers
#define CP16(s, g) \
  asm volatile("cp.async.cg.shared.global [%0], [%1], 16;" :: "r"(s), "l"(g))
#define CP_COMMIT() asm volatile("cp.async.commit_group;" ::: "memory")
#define CP_WAIT0() asm volatile("cp.async.wait_group 0;" ::: "memory")
#define CP_WAIT1() asm volatile("cp.async.wait_group 1;" ::: "memory")

// ======================= masks =======================
__device__ __forceinline__ bool read_mask(const void* p, int i, int f) {
  if (f == 0) return ((const unsigned char*)p)[i] != 0;
  if (f == 1) return ((const int*)p)[i] != 0;
  return ((const float*)p)[i] != 0.0f;
}
__global__ void detect_kernel(const unsigned char* __restrict__ p) {
  int big = 0, off = 0;
  for (int i = 0; i < 1024; ++i) {
    unsigned char c = p[i];
    big |= (c > 1) ? 1 : 0;
    off |= (c != 0 && (i & 3) != 0) ? 1 : 0;
  }
  g_flag = big ? 2 : (off ? 0 : 1);
}
__global__ void mask_kernel(const void* __restrict__ mp, const void* __restrict__ md,
                            float* __restrict__ outMP, float* __restrict__ outMD) {
  int f = g_flag;
  int idx = blockIdx.x * blockDim.x + threadIdx.x;
  if (idx < NB * GPNUM) {
    int b = idx / GPNUM, g = idx % GPNUM;
    int base = b * LP + g * 4;
    bool any = false;
#pragma unroll
    for (int r = 0; r < 4; ++r) any = any || read_mask(mp, base + r, f);
    g_masks[idx] = any ? 1 : 0;
    outMP[idx] = any ? 1.0f : 0.0f;
  } else {
    int j = idx - NB * GPNUM;
    if (j < NB * LDRG) {
      bool v = read_mask(md, j, f);
      g_masks[16384 + j] = v ? 1 : 0;
      outMD[j] = v ? 1.0f : 0.0f;
    }
  }
}

// ============== grouping + conversions (ILP x4) ==============
__global__ void group_bf16_v4(const float* __restrict__ P,
                              uint2* __restrict__ H, uint2* __restrict__ L) {
#pragma unroll
  for (int it = 0; it < 4; ++it) {
    int idx = blockIdx.x * 1024 + it * 256 + threadIdx.x;
    int d4 = idx & 127;
    int g = (idx >> 7) & 511;
    int b = idx >> 16;
    const float* p = P + ((size_t)b * LP + (size_t)g * 4) * DD + d4 * 4;
    float4 x0 = *(const float4*)p;
    float4 x1 = *(const float4*)(p + 512);
    float4 x2 = *(const float4*)(p + 1024);
    float4 x3 = *(const float4*)(p + 1536);
    float v0 = 0.25f * (x0.x + x1.x + x2.x + x3.x);
    float v1 = 0.25f * (x0.y + x1.y + x2.y + x3.y);
    float v2 = 0.25f * (x0.z + x1.z + x2.z + x3.z);
    float v3 = 0.25f * (x0.w + x1.w + x2.w + x3.w);
    uint32_t h01, l01, h23, l23;
    split2(v0, v1, h01, l01);
    split2(v2, v3, h23, l23);
    H[idx] = make_uint2(h01, h23);
    L[idx] = make_uint2(l01, l23);
  }
}

__global__ void cvt_bf16_v4(const float4* __restrict__ X, int n4,
                            uint2* __restrict__ H, uint2* __restrict__ L) {
#pragma unroll
  for (int it = 0; it < 4; ++it) {
    int i = blockIdx.x * 1024 + it * 256 + threadIdx.x;
    if (i >= n4) continue;
    float4 x = X[i];
    uint32_t h01, l01, h23, l23;
    split2(x.x, x.y, h01, l01);
    split2(x.z, x.w, h23, l23);
    H[i] = make_uint2(h01, h23);
    L[i] = make_uint2(l01, l23);
  }
}

__global__ void cvt_w6(const float4* w0, const float4* w1, const float4* w2,
                       const float4* w3, const float4* w4, const float4* w5,
                       uint2* __restrict__ H, uint2* __restrict__ L) {
  int wi = blockIdx.y;
  const float4* X = (wi == 0) ? w0 : (wi == 1) ? w1 : (wi == 2) ? w2
                   : (wi == 3) ? w3 : (wi == 4) ? w4 : w5;
#pragma unroll
  for (int it = 0; it < 4; ++it) {
    int i = blockIdx.x * 1024 + it * 256 + threadIdx.x;   // 65536 float4 per weight
    float4 x = X[i];
    uint32_t h01, l01, h23, l23;
    split2(x.x, x.y, h01, l01);
    split2(x.z, x.w, h23, l23);
    size_t o = (size_t)wi * 65536 + i;
    H[o] = make_uint2(h01, h23);
    L[o] = make_uint2(l01, l23);
  }
}

// ======================= MMA / ldmatrix macros =======================
#define MMA_BF16(c, a, b)                                                      \
  asm volatile("mma.sync.aligned.m16n8k16.row.col.f32.bf16.bf16.f32 "          \
               "{%0,%1,%2,%3}, {%4,%5,%6,%7}, {%8,%9}, {%0,%1,%2,%3};"         \
               : "+f"((c)[0]), "+f"((c)[1]), "+f"((c)[2]), "+f"((c)[3])        \
               : "r"((a)[0]), "r"((a)[1]), "r"((a)[2]), "r"((a)[3]),           \
                 "r"((b)[0]), "r"((b)[1]))

#define LDSM_X4(r0, r1, r2, r3, a)                                             \
  asm volatile("ldmatrix.sync.aligned.m8n8.x4.shared.b16 {%0,%1,%2,%3}, [%4];" \
               : "=r"(r0), "=r"(r1), "=r"(r2), "=r"(r3) : "r"(a))

#define LDSM_X4_T(r0, r1, r2, r3, a)                                           \
  asm volatile("ldmatrix.sync.aligned.m8n8.x4.trans.shared.b16 {%0,%1,%2,%3}, [%4];" \
               : "=r"(r0), "=r"(r1), "=r"(r2), "=r"(r3) : "r"(a))

// ====== bf16x3 projection (cp.async double-buffered) ======
#define PROJ_SMEM 61440
__global__ __launch_bounds__(256) void gemm_proj_mma(
    const u16* __restrict__ Ah, const u16* __restrict__ Al,
    const u16* __restrict__ Wh, const u16* __restrict__ Wl,
    u16* __restrict__ Ch, u16* __restrict__ Cl) {
  extern __shared__ __align__(16) u16 dyn[];
  u16* AhB = dyn;
  u16* AlB = dyn + 10240;
  u16* BhB = dyn + 20480;
  u16* BlB = dyn + 25600;

  const int tid = threadIdx.x;
  const int w = tid >> 5, lane = tid & 31;
  const int g = lane >> 2, t4 = lane & 3;
  const int wm = (w >> 1) * 32, wn = (w & 1) * 32;
  const int mBase = blockIdx.x * 128;
  const int nBase = blockIdx.y * 64;

  const int lane15 = lane & 15;
  const int hi8 = (lane >> 4) << 3;
  const uint32_t aAddrH = smaddr(AhB + (wm + lane15) * 40 + hi8);
  const uint32_t aAddrL = smaddr(AlB + (wm + lane15) * 40 + hi8);
  const int bn = (lane & 7) + hi8;
  const int bk = lane & 8;
  const uint32_t bAddrH = smaddr(BhB + (wn + bn) * 40 + bk);
  const uint32_t bAddrL = smaddr(BlB + (wn + bn) * 40 + bk);

  auto loadTile = [&](int k0, int buf) {
#pragma unroll
    for (int u = tid; u < 512; u += 256) {
      int row = u >> 2, seg = u & 3;
      size_t ga = (size_t)(mBase + row) * 512 + k0 + seg * 8;
      int so = buf * 5120 + row * 40 + seg * 8;
      CP16(smaddr(AhB + so), Ah + ga);
      CP16(smaddr(AlB + so), Al + ga);
    }
    {
      int row = tid >> 2, seg = tid & 3;
      size_t ga = (size_t)(nBase + row) * 512 + k0 + seg * 8;
      int so = buf * 2560 + row * 40 + seg * 8;
      CP16(smaddr(BhB + so), Wh + ga);
      CP16(smaddr(BlB + so), Wl + ga);
    }
    CP_COMMIT();
  };

  float acc[2][4][4];
#pragma unroll
  for (int mi = 0; mi < 2; ++mi)
#pragma unroll
    for (int j = 0; j < 4; ++j)
#pragma unroll
      for (int q = 0; q < 4; ++q) acc[mi][j][q] = 0.0f;

  loadTile(0, 0);
  for (int t = 0; t < 16; ++t) {
    if (t < 15) { loadTile((t + 1) * 32, (t + 1) & 1); CP_WAIT1(); }
    else CP_WAIT0();
    __syncthreads();
    const uint32_t aOff = (uint32_t)((t & 1) * 10240);
    const uint32_t bOff = (uint32_t)((t & 1) * 5120);
#pragma unroll
    for (int kk = 0; kk < 32; kk += 16) {
      uint32_t ah[2][4], al[2][4];
#pragma unroll
      for (int mi = 0; mi < 2; ++mi) {
        LDSM_X4(ah[mi][0], ah[mi][1], ah[mi][2], ah[mi][3], aAddrH + aOff + (mi * 640 + kk) * 2);
        LDSM_X4(al[mi][0], al[mi][1], al[mi][2], al[mi][3], aAddrL + aOff + (mi * 640 + kk) * 2);
      }
      uint32_t bh[4][2], bl[4][2];
#pragma unroll
      for (int p = 0; p < 2; ++p) {
        LDSM_X4(bh[2 * p][0], bh[2 * p][1], bh[2 * p + 1][0], bh[2 * p + 1][1],
                bAddrH + bOff + (p * 640 + kk) * 2);
        LDSM_X4(bl[2 * p][0], bl[2 * p][1], bl[2 * p + 1][0], bl[2 * p + 1][1],
                bAddrL + bOff + (p * 640 + kk) * 2);
      }
#pragma unroll
      for (int mi = 0; mi < 2; ++mi)
#pragma unroll
        for (int j = 0; j < 4; ++j) {
          MMA_BF16(acc[mi][j], ah[mi], bh[j]);
          MMA_BF16(acc[mi][j], ah[mi], bl[j]);
          MMA_BF16(acc[mi][j], al[mi], bh[j]);
        }
    }
    __syncthreads();
  }

#pragma unroll
  for (int mi = 0; mi < 2; ++mi) {
    int row = mBase + wm + mi * 16 + g;
#pragma unroll
    for (int j = 0; j < 4; ++j) {
      int col = nBase + wn + j * 8 + t4 * 2;
      uint32_t hi, lo;
      split2(acc[mi][j][0], acc[mi][j][1], hi, lo);
      *(uint32_t*)(Ch + (size_t)row * 512 + col) = hi;
      *(uint32_t*)(Cl + (size_t)row * 512 + col) = lo;
      split2(acc[mi][j][2], acc[mi][j][3], hi, lo);
      *(uint32_t*)(Ch + (size_t)(row + 8) * 512 + col) = hi;
      *(uint32_t*)(Cl + (size_t)(row + 8) * 512 + col) = lo;
    }
  }
}

// ====== bf16x3 logits (cp.async double-buffered, T=2): masked fp32 out ======
#define LOGITS_SMEM 61440
__global__ __launch_bounds__(256) void gemm_logits_mma(
    const u16* __restrict__ Qh, const u16* __restrict__ Ql,
    const u16* __restrict__ Kh, const u16* __restrict__ Kl,
    float* __restrict__ S,
    const unsigned char* __restrict__ mq, const unsigned char* __restrict__ mk,
    int Lq, int Lk) {
  extern __shared__ __align__(16) u16 dyn[];
  u16* AhB = dyn;
  u16* AlB = dyn + 10240;
  u16* BhB = dyn + 20480;
  u16* BlB = dyn + 25600;

  const int tid = threadIdx.x;
  const int w = tid >> 5, lane = tid & 31;
  const int g = lane >> 2, t4 = lane & 3;
  const int wm = (w >> 1) * 32, wn = (w & 1) * 32;
  const int mBase = blockIdx.x * 128;
  const int nBase = blockIdx.y * 64;
  const int z = blockIdx.z;
  const int b = z >> 3, h = z & 7;
  const u16* Ahg = Qh + (size_t)b * Lq * 512 + h * 64;
  const u16* Alg = Ql + (size_t)b * Lq * 512 + h * 64;
  const u16* Bhg = Kh + (size_t)b * Lk * 512 + h * 64;
  const u16* Blg = Kl + (size_t)b * Lk * 512 + h * 64;
  float* C = S + (size_t)z * Lq * Lk;
  const unsigned char* mqb = mq + b * Lq;
  const unsigned char* mkb = mk + b * Lk;

  const int lane15 = lane & 15;
  const int hi8 = (lane >> 4) << 3;
  const uint32_t aAddrH = smaddr(AhB + (wm + lane15) * 40 + hi8);
  const uint32_t aAddrL = smaddr(AlB + (wm + lane15) * 40 + hi8);
  const int bn = (lane & 7) + hi8;
  const int bk = lane & 8;
  const uint32_t bAddrH = smaddr(BhB + (wn + bn) * 40 + bk);
  const uint32_t bAddrL = smaddr(BlB + (wn + bn) * 40 + bk);

  auto loadTile = [&](int k0, int buf) {
#pragma unroll
    for (int u = tid; u < 512; u += 256) {
      int row = u >> 2, seg = u & 3;
      size_t ga = (size_t)(mBase + row) * 512 + k0 + seg * 8;
      int so = buf * 5120 + row * 40 + seg * 8;
      CP16(smaddr(AhB + so), Ahg + ga);
      CP16(smaddr(AlB + so), Alg + ga);
    }
    {
      int row = tid >> 2, seg = tid & 3;
      size_t ga = (size_t)(nBase + row) * 512 + k0 + seg * 8;
      int so = buf * 2560 + row * 40 + seg * 8;
      CP16(smaddr(BhB + so), Bhg + ga);
      CP16(smaddr(BlB + so), Blg + ga);
    }
    CP_COMMIT();
  };

  float acc[2][4][4];
#pragma unroll
  for (int mi = 0; mi < 2; ++mi)
#pragma unroll
    for (int j = 0; j < 4; ++j)
#pragma unroll
      for (int q = 0; q < 4; ++q) acc[mi][j][q] = 0.0f;

  loadTile(0, 0);
#pragma unroll
  for (int t = 0; t < 2; ++t) {
    if (t < 1) { loadTile(32, 1); CP_WAIT1(); }
    else CP_WAIT0();
    __syncthreads();
    const uint32_t aOff = (uint32_t)(t * 10240);
    const uint32_t bOff = (uint32_t)(t * 5120);
#pragma unroll
    for (int kk = 0; kk < 32; kk += 16) {
      uint32_t ah[2][4], al[2][4];
#pragma unroll
      for (int mi = 0; mi < 2; ++mi) {
        LDSM_X4(ah[mi][0], ah[mi][1], ah[mi][2], ah[mi][3], aAddrH + aOff + (mi * 640 + kk) * 2);
        LDSM_X4(al[mi][0], al[mi][1], al[mi][2], al[mi][3], aAddrL + aOff + (mi * 640 + kk) * 2);
      }
      uint32_t bh[4][2], bl[4][2];
#pragma unroll
      for (int p = 0; p < 2; ++p) {
        LDSM_X4(bh[2 * p][0], bh[2 * p][1], bh[2 * p + 1][0], bh[2 * p + 1][1],
                bAddrH + bOff + (p * 640 + kk) * 2);
        LDSM_X4(bl[2 * p][0], bl[2 * p][1], bl[2 * p + 1][0], bl[2 * p + 1][1],
                bAddrL + bOff + (p * 640 + kk) * 2);
      }
#pragma unroll
      for (int mi = 0; mi < 2; ++mi)
#pragma unroll
        for (int j = 0; j < 4; ++j) {
          MMA_BF16(acc[mi][j], ah[mi], bh[j]);
          MMA_BF16(acc[mi][j], ah[mi], bl[j]);
          MMA_BF16(acc[mi][j], al[mi], bh[j]);
        }
    }
    __syncthreads();
  }

#pragma unroll
  for (int mi = 0; mi < 2; ++mi) {
    int row = mBase + wm + mi * 16 + g;
    float p0 = mqb[row] ? 0.0f : 1.0e6f;
    float p1 = mqb[row + 8] ? 0.0f : 1.0e6f;
#pragma unroll
    for (int j = 0; j < 4; ++j) {
      int col = nBase + wn + j * 8 + t4 * 2;
      float c0 = mkb[col] ? 0.0f : 1.0e6f;
      float c1 = mkb[col + 1] ? 0.0f : 1.0e6f;
      *(float2*)(C + (size_t)row * Lk + col) =
          make_float2(acc[mi][j][0] - fmaxf(p0, c0), acc[mi][j][1] - fmaxf(p0, c1));
      *(float2*)(C + (size_t)(row + 8) * Lk + col) =
          make_float2(acc[mi][j][2] - fmaxf(p1, c0), acc[mi][j][3] - fmaxf(p1, c1));
    }
  }
}

// ---------------- softmax ----------------
template <int LK>
__global__ __launch_bounds__(256) void softmax_kernel(
    float* __restrict__ S, const unsigned char* __restrict__ mq,
    float* __restrict__ alphaOut, int Lq) {
  __shared__ float sbuf[8][LK + 1];
  const int l = blockIdx.x, b = blockIdx.y;
  const int tid = threadIdx.x, w = tid >> 5, lane = tid & 31;
  const size_t abase = ((size_t)b * Lq + l) * (size_t)(LK * 8);

  if (!mq[b * Lq + l]) {
    for (int idx = tid; idx < LK * 8; idx += 256) alphaOut[abase + idx] = 0.0f;
#pragma unroll
    for (int h = 0; h < 8; ++h) {
      float* srow = S + ((size_t)(b * 8 + h) * Lq + l) * LK;
      for (int k = tid; k < LK; k += 256) srow[k] = 0.0f;
    }
    return;
  }

  float* srow = S + ((size_t)(b * 8 + w) * Lq + l) * LK;
  const int nit = LK / 32;
  float v[LK / 32];
  float mx = -3.0e38f;
#pragma unroll
  for (int i = 0; i < nit; ++i) { v[i] = srow[lane + 32 * i]; mx = fmaxf(mx, v[i]); }
#pragma unroll
  for (int o = 16; o > 0; o >>= 1) mx = fmaxf(mx, __shfl_xor_sync(0xffffffffu, mx, o));
  float sum = 0.0f;
#pragma unroll
  for (int i = 0; i < nit; ++i) { float e = __expf(v[i] - mx); v[i] = e; sum += e; }
#pragma unroll
  for (int o = 16; o > 0; o >>= 1) sum += __shfl_xor_sync(0xffffffffu, sum, o);
  float inv = 1.0f / sum;
  u16* arow = (u16*)srow;
#pragma unroll
  for (int i = 0; i < nit; ++i) {
    float a = v[i] * inv;
    sbuf[w][lane + 32 * i] = a;
    u16 hb = bf16bits(a);
    arow[lane + 32 * i] = hb;
    arow[LK + lane + 32 * i] = bf16bits(a - bf16val(hb));
  }
  __syncthreads();
#pragma unroll 4
  for (int idx = tid; idx < LK * 8; idx += 256) {
    int k = idx >> 3, h = idx & 7;
    alphaOut[abase + idx] = sbuf[h][k];
  }
}

// ====== bf16x3 AV (cp.async double-buffered) ======
#define AV_SMEM 59392
__global__ __launch_bounds__(256) void gemm_av_mma(
    const float* __restrict__ S, const u16* __restrict__ Vh, const u16* __restrict__ Vl,
    float* __restrict__ Out, int Lq, int Lk) {
  extern __shared__ __align__(16) u16 dyn[];
  u16* AhB = dyn;
  u16* AlB = dyn + 10240;
  u16* BhB = dyn + 20480;
  u16* BlB = dyn + 25088;

  const int tid = threadIdx.x;
  const int w = tid >> 5, lane = tid & 31;
  const int g = lane >> 2, t4 = lane & 3;
  const int wm = (w >> 1) * 32, wn = (w & 1) * 32;
  const int mBase = blockIdx.x * 128;
  const int z = blockIdx.z;
  const int b = z >> 3, h = z & 7;
  const u16* Abase = (const u16*)(S + (size_t)z * Lq * Lk);
  const size_t vbase = (size_t)b * Lk * 512 + h * 64;
  float* C = Out + (size_t)b * Lq * 512 + h * 64;

  const int lane15 = lane & 15;
  const int hi8 = (lane >> 4) << 3;
  const uint32_t aAddrH = smaddr(AhB + (wm + lane15) * 40 + hi8);
  const uint32_t aAddrL = smaddr(AlB + (wm + lane15) * 40 + hi8);
  const int bkOff = (lane & 7) + (lane & 8);
  const uint32_t bAddrH = smaddr(BhB + bkOff * 72 + wn + hi8);
  const uint32_t bAddrL = smaddr(BlB + bkOff * 72 + wn + hi8);

  auto loadTile = [&](int k0, int buf) {
#pragma unroll
    for (int u = tid; u < 512; u += 256) {
      int row = u >> 2, seg = u & 3;
      const u16* ar = Abase + (size_t)(mBase + row) * 2 * Lk + k0 + seg * 8;
      int so = buf * 5120 + row * 40 + seg * 8;
      CP16(smaddr(AhB + so), ar);
      CP16(smaddr(AlB + so), ar + Lk);
    }
    {
      int row = tid >> 3, seg = tid & 7;
      size_t ga = vbase + (size_t)(k0 + row) * 512 + seg * 8;
      int so = buf * 2304 + row * 72 + seg * 8;
      CP16(smaddr(BhB + so), Vh + ga);
      CP16(smaddr(BlB + so), Vl + ga);
    }
    CP_COMMIT();
  };

  float acc[2][4][4];
#pragma unroll
  for (int mi = 0; mi < 2; ++mi)
#pragma unroll
    for (int j = 0; j < 4; ++j)
#pragma unroll
      for (int q = 0; q < 4; ++q) acc[mi][j][q] = 0.0f;

  const int T = Lk / 32;
  loadTile(0, 0);
  for (int t = 0; t < T; ++t) {
    if (t < T - 1) { loadTile((t + 1) * 32, (t + 1) & 1); CP_WAIT1(); }
    else CP_WAIT0();
    __syncthreads();
    const uint32_t aOff = (uint32_t)((t & 1) * 10240);
    const uint32_t bOff = (uint32_t)((t & 1) * 4608);
#pragma unroll
    for (int kk = 0; kk < 32; kk += 16) {
      uint32_t ah[2][4], al[2][4];
#pragma unroll
      for (int mi = 0; mi < 2; ++mi) {
        LDSM_X4(ah[mi][0], ah[mi][1], ah[mi][2], ah[mi][3], aAddrH + aOff + (mi * 640 + kk) * 2);
        LDSM_X4(al[mi][0], al[mi][1], al[mi][2], al[mi][3], aAddrL + aOff + (mi * 640 + kk) * 2);
      }
      uint32_t bh[4][2], bl[4][2];
#pragma unroll
      for (int p = 0; p < 2; ++p) {
        LDSM_X4_T(bh[2 * p][0], bh[2 * p][1], bh[2 * p + 1][0], bh[2 * p + 1][1],
                  bAddrH + bOff + (kk * 72 + p * 16) * 2);
        LDSM_X4_T(bl[2 * p][0], bl[2 * p][1], bl[2 * p + 1][0], bl[2 * p + 1][1],
                  bAddrL + bOff + (kk * 72 + p * 16) * 2);
      }
#pragma unroll
      for (int mi = 0; mi < 2; ++mi)
#pragma unroll
        for (int j = 0; j < 4; ++j) {
          MMA_BF16(acc[mi][j], ah[mi], bh[j]);
          MMA_BF16(acc[mi][j], ah[mi], bl[j]);
          MMA_BF16(acc[mi][j], al[mi], bh[j]);
        }
    }
    __syncthreads();
  }

#pragma unroll
  for (int mi = 0; mi < 2; ++mi) {
    int row = mBase + wm + mi * 16 + g;
#pragma unroll
    for (int j = 0; j < 4; ++j) {
      int col = wn + j * 8 + t4 * 2;
      *(float2*)(C + (size_t)row * 512 + col) = make_float2(acc[mi][j][0], acc[mi][j][1]);
      *(float2*)(C + (size_t)(row + 8) * 512 + col) = make_float2(acc[mi][j][2], acc[mi][j][3]);
    }
  }
}

// ---------------- launch ----------------
extern "C" void kernel_launch(void* const* d_in, const int* in_sizes, int n_in,
                              void* d_out, int out_size) {
  const float* protein = (const float*)d_in[0];
  const float* drug    = (const float*)d_in[1];
  const void*  mpraw   = d_in[2];
  const void*  mdraw   = d_in[3];
  const float* W[6] = {(const float*)d_in[4], (const float*)d_in[5], (const float*)d_in[6],
                       (const float*)d_in[7], (const float*)d_in[8], (const float*)d_in[9]};
  float* out = (float*)d_out;

  float* sc = nullptr;
  cudaGetSymbolAddress((void**)&sc, g_scratch);
  unsigned char* mg = nullptr;
  cudaGetSymbolAddress((void**)&mg, g_masks);

  float* Sb = sc;
  u16* QPh = (u16*)(sc + 33554432); u16* QPl = (u16*)(sc + 37748736);
  u16* KPh = (u16*)(sc + 41943040); u16* KPl = (u16*)(sc + 46137344);
  u16* VPh = (u16*)(sc + 50331648); u16* VPl = (u16*)(sc + 54525952);
  u16* QDh = (u16*)(sc + 58720256); u16* QDl = (u16*)(sc + 60817408);
  u16* KDh = (u16*)(sc + 62914560); u16* KDl = (u16*)(sc + 65011712);
  u16* VDh = (u16*)(sc + 67108864); u16* VDl = (u16*)(sc + 69206016);
  u16* PGH = (u16*)(sc + 71303168); u16* PGL = (u16*)(sc + 75497472);
  u16* DRH = (u16*)(sc + 79691776); u16* DRL = (u16*)(sc + 81788928);
  u16* WHb = (u16*)(sc + 83886080); u16* WLb = (u16*)(sc + 84672512);
  unsigned char* mpg = mg;
  unsigned char* mdg = mg + 16384;

  const size_t OFF_PROT = 0;
  const size_t OFF_DRUG = 8388608;
  const size_t OFF_MP   = 12582912;
  const size_t OFF_MD   = 12599296;
  const size_t OFF_APD  = 12607488;
  const size_t OFF_ADP  = 46161920;

  static int attr_done = 0;
  if (!attr_done) {
    cudaFuncSetAttribute(gemm_proj_mma, cudaFuncAttributeMaxDynamicSharedMemorySize, PROJ_SMEM);
    cudaFuncSetAttribute(gemm_logits_mma, cudaFuncAttributeMaxDynamicSharedMemorySize, LOGITS_SMEM);
    cudaFuncSetAttribute(gemm_av_mma, cudaFuncAttributeMaxDynamicSharedMemorySize, AV_SMEM);
    attr_done = 1;
  }

  detect_kernel<<<1, 1>>>((const unsigned char*)mpraw);
  mask_kernel<<<96, 256>>>(mpraw, mdraw, out + OFF_MP, out + OFF_MD);
  group_bf16_v4<<<2048, 256>>>(protein, (uint2*)PGH, (uint2*)PGL);
  cvt_bf16_v4<<<1024, 256>>>((const float4*)drug, 1048576, (uint2*)DRH, (uint2*)DRL);
  cvt_w6<<<dim3(64, 6), 256>>>((const float4*)W[0], (const float4*)W[1], (const float4*)W[2],
                               (const float4*)W[3], (const float4*)W[4], (const float4*)W[5],
                               (uint2*)WHb, (uint2*)WLb);

  // projections -> bf16 hi/lo
  u16* PH[3] = {QPh, KPh, VPh}; u16* PL[3] = {QPl, KPl, VPl};
  for (int i = 0; i < 3; ++i)
    gemm_proj_mma<<<dim3(128, 8), 256, PROJ_SMEM>>>(PGH, PGL, WHb + (size_t)i * 262144,
                                                    WLb + (size_t)i * 262144, PH[i], PL[i]);
  u16* DH[3] = {QDh, KDh, VDh}; u16* DL[3] = {QDl, KDl, VDl};
  for (int i = 0; i < 3; ++i)
    gemm_proj_mma<<<dim3(64, 8), 256, PROJ_SMEM>>>(DRH, DRL, WHb + (size_t)(i + 3) * 262144,
                                                   WLb + (size_t)(i + 3) * 262144, DH[i], DL[i]);

  // protein->drug: Lq=512, Lk=256
  gemm_logits_mma<<<dim3(4, 4, 256), 256, LOGITS_SMEM>>>(QPh, QPl, KDh, KDl, Sb, mpg, mdg, 512, 256);
  softmax_kernel<256><<<dim3(512, 32), 256>>>(Sb, mpg, out + OFF_APD, 512);
  gemm_av_mma<<<dim3(4, 1, 256), 256, AV_SMEM>>>(Sb, VDh, VDl, out + OFF_PROT, 512, 256);

  // drug->protein: Lq=256, Lk=512
  gemm_logits_mma<<<dim3(2, 8, 256), 256, LOGITS_SMEM>>>(QDh, QDl, KPh, KPl, Sb, mdg, mpg, 256, 512);
  softmax_kernel<512><<<dim3(256, 32), 256>>>(Sb, mdg, out + OFF_ADP, 256);
  gemm_av_mma<<<dim3(2, 1, 256), 256, AV_SMEM>>>(Sb, VPh, VPl, out + OFF_DRUG, 256, 512);

  (void)in_sizes; (void)n_in; (void)out_size;
}